// round 1
// baseline (speedup 1.0000x reference)
#include <cuda_runtime.h>
#include <cuda_bf16.h>
#include <cstdint>

// Problem constants (fixed by reference)
#define N_ENT 50000
#define N_REL 500
#define N_TOT (N_ENT + N_REL)   // 50500
#define E_NUM 800000
#define D_IN  100
#define D_OUT 200
#define ALPHA 0.2f
#define EPSN  1e-12f

// ---------------- scratch (device globals; no runtime alloc) ----------------
__device__ float g_htmp[N_TOT * D_OUT];   // pre-aggregation projection
__device__ float g_h1[N_TOT * D_OUT];     // layer-1 output
__device__ int   g_counts[N_TOT];
__device__ int   g_starts[N_TOT + 1];
__device__ int   g_cursor[N_TOT];
__device__ int   g_src[E_NUM];            // dst-sorted source indices
__device__ float g_val[E_NUM];            // dst-sorted edge values
__device__ int   g_is64;                  // 1 if edge_index is int64, 0 if int32

// ---------------- helpers ----------------
__device__ __forceinline__ unsigned long long fma2(unsigned long long a,
                                                   unsigned long long b,
                                                   unsigned long long c) {
    unsigned long long d;
    asm("fma.rn.f32x2 %0, %1, %2, %3;" : "=l"(d) : "l"(a), "l"(b), "l"(c));
    return d;
}
__device__ __forceinline__ unsigned long long pack2(float x) {
    unsigned long long d;
    asm("mov.b64 %0, {%1, %1};" : "=l"(d) : "f"(x));
    return d;
}
__device__ __forceinline__ int load_idx(const void* ei, long long i, int is64) {
    if (is64) return (int)(((const long long*)ei)[i]);
    return ((const int*)ei)[i];
}

// ---------------- dtype detection for edge_index ----------------
// int64 little-endian with values in [0, 50500) => every odd 32-bit word is 0.
__global__ void detect_kernel(const int* __restrict__ ei_words) {
    if (threadIdx.x == 0 && blockIdx.x == 0) {
        int f = 1;
        for (int i = 1; i < 256; i += 2) {
            if (ei_words[i] != 0) { f = 0; break; }
        }
        g_is64 = f;
    }
}

// ---------------- CSR build ----------------
__global__ void zero_counts_kernel() {
    int i = blockIdx.x * blockDim.x + threadIdx.x;
    if (i < N_TOT) g_counts[i] = 0;
}

__global__ void hist_kernel(const void* __restrict__ ei) {
    int e = blockIdx.x * blockDim.x + threadIdx.x;
    if (e < E_NUM) {
        int is64 = g_is64;
        int d = load_idx(ei, (long long)E_NUM + e, is64);
        atomicAdd(&g_counts[d], 1);
    }
}

// Single-block exclusive scan over g_counts -> g_starts, g_cursor.
__global__ void scan_kernel() {
    __shared__ int woff[32];
    __shared__ int tot_s;
    const int tid = threadIdx.x;
    const int lane = tid & 31;
    const int wid = tid >> 5;
    int carry = 0;
    for (int base = 0; base < N_TOT; base += 1024) {
        int i = base + tid;
        int v = (i < N_TOT) ? g_counts[i] : 0;
        // warp inclusive scan
        int incl = v;
        #pragma unroll
        for (int o = 1; o < 32; o <<= 1) {
            int t = __shfl_up_sync(0xffffffffu, incl, o);
            if (lane >= o) incl += t;
        }
        if (lane == 31) woff[wid] = incl;
        __syncthreads();
        if (wid == 0) {
            int w = woff[lane];
            int wincl = w;
            #pragma unroll
            for (int o = 1; o < 32; o <<= 1) {
                int t = __shfl_up_sync(0xffffffffu, wincl, o);
                if (lane >= o) wincl += t;
            }
            woff[lane] = wincl - w;   // exclusive warp offset
            if (lane == 31) tot_s = wincl;
        }
        __syncthreads();
        int ex = carry + woff[wid] + (incl - v);
        if (i < N_TOT) { g_starts[i] = ex; g_cursor[i] = ex; }
        carry += tot_s;
        __syncthreads();
    }
    if (tid == 0) g_starts[N_TOT] = carry;
}

__global__ void scatter_kernel(const void* __restrict__ ei,
                               const float* __restrict__ ev) {
    int e = blockIdx.x * blockDim.x + threadIdx.x;
    if (e < E_NUM) {
        int is64 = g_is64;
        int s = load_idx(ei, e, is64);
        int d = load_idx(ei, (long long)E_NUM + e, is64);
        int pos = atomicAdd(&g_cursor[d], 1);
        g_src[pos] = s;
        g_val[pos] = ev[e];
    }
}

// ---------------- GEMM: C[N,200] = A[N,K] * W[K,200] (fp32, f32x2 FMAs) ----
// Block: (25,8) = 200 threads, computes 64 rows x 200 cols.
// Thread tile: 8 rows x 8 cols (as 4 f32x2 column pairs).
template <int K>
__global__ void __launch_bounds__(200)
gemm_kernel(const float* __restrict__ A, const float* __restrict__ W,
            float* __restrict__ C, int nRows) {
    __shared__ float a_s[25][64];
    __shared__ float w_s[25][200];
    const int tx = threadIdx.x;            // 0..24 -> cols tx*8..tx*8+7
    const int ty = threadIdx.y;            // 0..7  -> rows ty*8..ty*8+7
    const int tid = ty * 25 + tx;          // 0..199
    const int r0 = blockIdx.x * 64;

    unsigned long long acc[8][4];
    #pragma unroll
    for (int r = 0; r < 8; r++)
        #pragma unroll
        for (int c = 0; c < 4; c++) acc[r][c] = 0ull;

    #pragma unroll
    for (int kt = 0; kt < K / 25; kt++) {
        const int k0 = kt * 25;
        // A tile: 64 rows x 25 k, stored transposed a_s[k][row]
        #pragma unroll
        for (int i = 0; i < 8; i++) {
            int e = tid + i * 200;
            int row = e / 25;
            int kk = e % 25;
            int g = r0 + row;
            a_s[kk][row] = (g < nRows) ? A[(long long)g * K + k0 + kk] : 0.0f;
        }
        // W tile: 25 k x 200 cols
        #pragma unroll
        for (int kk = 0; kk < 25; kk++)
            w_s[kk][tid] = W[(k0 + kk) * 200 + tid];
        __syncthreads();

        #pragma unroll
        for (int kk = 0; kk < 25; kk++) {
            float4 a0 = *(const float4*)&a_s[kk][ty * 8];
            float4 a1 = *(const float4*)&a_s[kk][ty * 8 + 4];
            ulonglong2 w01 = *(const ulonglong2*)&w_s[kk][tx * 8];
            ulonglong2 w23 = *(const ulonglong2*)&w_s[kk][tx * 8 + 4];
            unsigned long long av[8];
            av[0] = pack2(a0.x); av[1] = pack2(a0.y);
            av[2] = pack2(a0.z); av[3] = pack2(a0.w);
            av[4] = pack2(a1.x); av[5] = pack2(a1.y);
            av[6] = pack2(a1.z); av[7] = pack2(a1.w);
            #pragma unroll
            for (int r = 0; r < 8; r++) {
                acc[r][0] = fma2(av[r], w01.x, acc[r][0]);
                acc[r][1] = fma2(av[r], w01.y, acc[r][1]);
                acc[r][2] = fma2(av[r], w23.x, acc[r][2]);
                acc[r][3] = fma2(av[r], w23.y, acc[r][3]);
            }
        }
        __syncthreads();
    }

    #pragma unroll
    for (int r = 0; r < 8; r++) {
        int g = r0 + ty * 8 + r;
        if (g < nRows) {
            ulonglong2 s0 = make_ulonglong2(acc[r][0], acc[r][1]);
            ulonglong2 s1 = make_ulonglong2(acc[r][2], acc[r][3]);
            *(ulonglong2*)&C[(long long)g * 200 + tx * 8] = s0;
            *(ulonglong2*)&C[(long long)g * 200 + tx * 8 + 4] = s1;
        }
    }
}

// ---------------- Aggregation: one block per dst row, no atomics ----------
// out[r,:] = leaky( sum_{edges e with dst=r} h[src[e],:] * val[e] )
// do_norm==1: additionally L2-normalize the row (final layer -> d_out).
__global__ void __launch_bounds__(64)
agg_kernel(const float4* __restrict__ h, float* __restrict__ out, int do_norm) {
    const int r = blockIdx.x;
    const int t = threadIdx.x;
    const bool act = t < 50;               // 50 float4 = 200 floats
    const int beg = g_starts[r];
    const int end = g_starts[r + 1];

    float4 acc = make_float4(0.f, 0.f, 0.f, 0.f);
    int i = beg;
    for (; i + 1 < end; i += 2) {
        int s0 = __ldg(&g_src[i]);
        int s1 = __ldg(&g_src[i + 1]);
        float v0 = __ldg(&g_val[i]);
        float v1 = __ldg(&g_val[i + 1]);
        if (act) {
            float4 x0 = __ldg(&h[(long long)s0 * 50 + t]);
            float4 x1 = __ldg(&h[(long long)s1 * 50 + t]);
            acc.x = fmaf(x0.x, v0, acc.x); acc.y = fmaf(x0.y, v0, acc.y);
            acc.z = fmaf(x0.z, v0, acc.z); acc.w = fmaf(x0.w, v0, acc.w);
            acc.x = fmaf(x1.x, v1, acc.x); acc.y = fmaf(x1.y, v1, acc.y);
            acc.z = fmaf(x1.z, v1, acc.z); acc.w = fmaf(x1.w, v1, acc.w);
        }
    }
    if (i < end) {
        int s0 = __ldg(&g_src[i]);
        float v0 = __ldg(&g_val[i]);
        if (act) {
            float4 x0 = __ldg(&h[(long long)s0 * 50 + t]);
            acc.x = fmaf(x0.x, v0, acc.x); acc.y = fmaf(x0.y, v0, acc.y);
            acc.z = fmaf(x0.z, v0, acc.z); acc.w = fmaf(x0.w, v0, acc.w);
        }
    }
    // LeakyReLU
    acc.x = acc.x > 0.f ? acc.x : ALPHA * acc.x;
    acc.y = acc.y > 0.f ? acc.y : ALPHA * acc.y;
    acc.z = acc.z > 0.f ? acc.z : ALPHA * acc.z;
    acc.w = acc.w > 0.f ? acc.w : ALPHA * acc.w;

    if (do_norm) {
        float ss = act ? (acc.x * acc.x + acc.y * acc.y +
                          acc.z * acc.z + acc.w * acc.w) : 0.f;
        #pragma unroll
        for (int o = 16; o; o >>= 1) ss += __shfl_down_sync(0xffffffffu, ss, o);
        __shared__ float sred[2];
        if ((t & 31) == 0) sred[t >> 5] = ss;
        __syncthreads();
        float tot = sred[0] + sred[1];
        float inv = 1.0f / fmaxf(sqrtf(tot), EPSN);
        acc.x *= inv; acc.y *= inv; acc.z *= inv; acc.w *= inv;
    }
    if (act) ((float4*)out)[(long long)r * 50 + t] = acc;
}

// ---------------- launch ----------------
extern "C" void kernel_launch(void* const* d_in, const int* in_sizes, int n_in,
                              void* d_out, int out_size) {
    const float* emb = (const float*)d_in[0];        // [N_TOT, 100]
    const float* W1  = (const float*)d_in[1];        // [100, 200]
    const float* W2  = (const float*)d_in[2];        // [200, 200]
    const void*  ei  = d_in[3];                      // [2, E] int64 or int32
    const float* ev  = (const float*)d_in[4];        // [E]
    float* out = (float*)d_out;                      // [N_TOT, 200]

    float* htmp; cudaGetSymbolAddress((void**)&htmp, g_htmp);
    float* h1;   cudaGetSymbolAddress((void**)&h1, g_h1);

    // CSR build
    detect_kernel<<<1, 32>>>((const int*)ei);
    zero_counts_kernel<<<(N_TOT + 255) / 256, 256>>>();
    hist_kernel<<<(E_NUM + 255) / 256, 256>>>(ei);
    scan_kernel<<<1, 1024>>>();
    scatter_kernel<<<(E_NUM + 255) / 256, 256>>>(ei, ev);

    dim3 gblock(25, 8);
    int ggrid = (N_TOT + 63) / 64;

    // Layer 1
    gemm_kernel<D_IN><<<ggrid, gblock>>>(emb, W1, htmp, N_TOT);
    agg_kernel<<<N_TOT, 64>>>((const float4*)htmp, h1, 0);

    // Layer 2 + normalize -> d_out
    gemm_kernel<D_OUT><<<ggrid, gblock>>>(h1, W2, htmp, N_TOT);
    agg_kernel<<<N_TOT, 64>>>((const float4*)htmp, out, 1);
}

// round 2
// speedup vs baseline: 1.0891x; 1.0891x over previous
#include <cuda_runtime.h>
#include <cuda_bf16.h>
#include <cstdint>

#define N_ENT 50000
#define N_REL 500
#define N_TOT (N_ENT + N_REL)   // 50500
#define E_NUM 800000
#define D_IN  100
#define D_OUT 200
#define ALPHA 0.2f
#define EPSN  1e-12f

#define SCAN_BLK 1024
#define SCAN_NB  ((N_TOT + SCAN_BLK - 1) / SCAN_BLK)   // 50

// ---------------- scratch (device globals; no runtime alloc) ----------------
__device__ float g_buf0[N_TOT * D_OUT];   // agg1 out [N,100] then gemm2 out [N,200]
__device__ float g_h1[N_TOT * D_OUT];     // layer-1 output [N,200]
__device__ int   g_counts[N_TOT];
__device__ int   g_starts[N_TOT + 1];
__device__ int   g_cursor[N_TOT];
__device__ int   g_bsum[SCAN_NB];
__device__ int   g_src[E_NUM];            // dst-sorted source indices
__device__ float g_val[E_NUM];            // dst-sorted edge values
__device__ int   g_is64;

// ---------------- helpers ----------------
__device__ __forceinline__ unsigned long long fma2(unsigned long long a,
                                                   unsigned long long b,
                                                   unsigned long long c) {
    unsigned long long d;
    asm("fma.rn.f32x2 %0, %1, %2, %3;" : "=l"(d) : "l"(a), "l"(b), "l"(c));
    return d;
}
__device__ __forceinline__ unsigned long long pack2(float x) {
    unsigned long long d;
    asm("mov.b64 %0, {%1, %1};" : "=l"(d) : "f"(x));
    return d;
}
__device__ __forceinline__ int load_idx(const void* ei, long long i, int is64) {
    if (is64) return (int)(((const long long*)ei)[i]);
    return ((const int*)ei)[i];
}

// ---------------- init: zero counts + dtype detect (fused) ----------------
__global__ void init_kernel(const int* __restrict__ ei_words) {
    int i = blockIdx.x * blockDim.x + threadIdx.x;
    if (i < N_TOT) g_counts[i] = 0;
    if (i == 0) {
        int f = 1;
        #pragma unroll 8
        for (int j = 1; j < 256; j += 2)
            if (ei_words[j] != 0) f = 0;
        g_is64 = f;
    }
}

__global__ void hist_kernel(const void* __restrict__ ei) {
    int e = blockIdx.x * blockDim.x + threadIdx.x;
    if (e < E_NUM) {
        int d = load_idx(ei, (long long)E_NUM + e, g_is64);
        atomicAdd(&g_counts[d], 1);
    }
}

// ---- scan pass 1: per-block exclusive scan, block sums to g_bsum ----
__global__ void __launch_bounds__(SCAN_BLK)
scan1_kernel() {
    __shared__ int woff[32];
    const int tid = threadIdx.x;
    const int lane = tid & 31;
    const int wid = tid >> 5;
    const int i = blockIdx.x * SCAN_BLK + tid;
    int v = (i < N_TOT) ? g_counts[i] : 0;
    int incl = v;
    #pragma unroll
    for (int o = 1; o < 32; o <<= 1) {
        int t = __shfl_up_sync(0xffffffffu, incl, o);
        if (lane >= o) incl += t;
    }
    if (lane == 31) woff[wid] = incl;
    __syncthreads();
    if (wid == 0) {
        int w = woff[lane];
        int wincl = w;
        #pragma unroll
        for (int o = 1; o < 32; o <<= 1) {
            int t = __shfl_up_sync(0xffffffffu, wincl, o);
            if (lane >= o) wincl += t;
        }
        woff[lane] = wincl - w;
        if (lane == 31) g_bsum[blockIdx.x] = wincl;
    }
    __syncthreads();
    if (i < N_TOT) g_starts[i] = woff[wid] + (incl - v);
}

// ---- scan pass 2: add block offsets (each block reduces bsum locally) ----
__global__ void __launch_bounds__(SCAN_BLK)
scan2_kernel() {
    __shared__ int s_off[2];
    const int tid = threadIdx.x;
    const int b = blockIdx.x;
    if (tid < 64) {
        int v = (tid < b) ? g_bsum[tid] : 0;
        #pragma unroll
        for (int o = 16; o; o >>= 1) v += __shfl_down_sync(0xffffffffu, v, o);
        if ((tid & 31) == 0) s_off[tid >> 5] = v;
    }
    __syncthreads();
    int off = s_off[0] + s_off[1];
    int i = b * SCAN_BLK + tid;
    if (i < N_TOT) {
        int s = g_starts[i] + off;
        g_starts[i] = s;
        g_cursor[i] = s;
    }
    if (b == SCAN_NB - 1 && tid == 0)
        g_starts[N_TOT] = off + g_bsum[b];
}

__global__ void scatter_kernel(const void* __restrict__ ei,
                               const float* __restrict__ ev) {
    int e = blockIdx.x * blockDim.x + threadIdx.x;
    if (e < E_NUM) {
        int is64 = g_is64;
        int s = load_idx(ei, e, is64);
        int d = load_idx(ei, (long long)E_NUM + e, is64);
        int pos = atomicAdd(&g_cursor[d], 1);
        g_src[pos] = s;
        g_val[pos] = ev[e];
    }
}

// ---------------- agg1: t1[r,0:100] = sum h[src]*val   (raw embeddings) ----
// 256 threads = 8 warp-groups; each warp owns one row; lanes 0..24 carry float4.
__global__ void __launch_bounds__(256)
agg1_kernel(const float4* __restrict__ h, float4* __restrict__ out, int nRows) {
    const int g = threadIdx.x >> 5;
    const int lane = threadIdx.x & 31;
    const int r = blockIdx.x * 8 + g;
    if (r >= nRows) return;
    const bool act = lane < 25;            // 25 float4 = 100 floats
    const int beg = g_starts[r];
    const int end = g_starts[r + 1];

    float4 acc = make_float4(0.f, 0.f, 0.f, 0.f);
    int i = beg;
    for (; i + 3 < end; i += 4) {
        int s0 = __ldg(&g_src[i]),     s1 = __ldg(&g_src[i + 1]);
        int s2 = __ldg(&g_src[i + 2]), s3 = __ldg(&g_src[i + 3]);
        float v0 = __ldg(&g_val[i]),     v1 = __ldg(&g_val[i + 1]);
        float v2 = __ldg(&g_val[i + 2]), v3 = __ldg(&g_val[i + 3]);
        if (act) {
            float4 x0 = __ldg(&h[(long long)s0 * 25 + lane]);
            float4 x1 = __ldg(&h[(long long)s1 * 25 + lane]);
            float4 x2 = __ldg(&h[(long long)s2 * 25 + lane]);
            float4 x3 = __ldg(&h[(long long)s3 * 25 + lane]);
            acc.x = fmaf(x0.x, v0, acc.x); acc.y = fmaf(x0.y, v0, acc.y);
            acc.z = fmaf(x0.z, v0, acc.z); acc.w = fmaf(x0.w, v0, acc.w);
            acc.x = fmaf(x1.x, v1, acc.x); acc.y = fmaf(x1.y, v1, acc.y);
            acc.z = fmaf(x1.z, v1, acc.z); acc.w = fmaf(x1.w, v1, acc.w);
            acc.x = fmaf(x2.x, v2, acc.x); acc.y = fmaf(x2.y, v2, acc.y);
            acc.z = fmaf(x2.z, v2, acc.z); acc.w = fmaf(x2.w, v2, acc.w);
            acc.x = fmaf(x3.x, v3, acc.x); acc.y = fmaf(x3.y, v3, acc.y);
            acc.z = fmaf(x3.z, v3, acc.z); acc.w = fmaf(x3.w, v3, acc.w);
        }
    }
    for (; i < end; i++) {
        int s0 = __ldg(&g_src[i]);
        float v0 = __ldg(&g_val[i]);
        if (act) {
            float4 x0 = __ldg(&h[(long long)s0 * 25 + lane]);
            acc.x = fmaf(x0.x, v0, acc.x); acc.y = fmaf(x0.y, v0, acc.y);
            acc.z = fmaf(x0.z, v0, acc.z); acc.w = fmaf(x0.w, v0, acc.w);
        }
    }
    if (act) out[(long long)r * 25 + lane] = acc;
}

// ---------------- GEMM: C[N,200] = act( A[N,K] * W[K,200] ) ----------------
// Block (25,8)=200 thr, 64 rows x 200 cols; thread tile 8x8 via f32x2 FMAs.
template <int K, bool LEAKY>
__global__ void __launch_bounds__(200)
gemm_kernel(const float* __restrict__ A, const float* __restrict__ W,
            float* __restrict__ C, int nRows) {
    __shared__ float a_s[25][64];
    __shared__ float w_s[25][200];
    const int tx = threadIdx.x;
    const int ty = threadIdx.y;
    const int tid = ty * 25 + tx;
    const int r0 = blockIdx.x * 64;

    unsigned long long acc[8][4];
    #pragma unroll
    for (int r = 0; r < 8; r++)
        #pragma unroll
        for (int c = 0; c < 4; c++) acc[r][c] = 0ull;

    #pragma unroll
    for (int kt = 0; kt < K / 25; kt++) {
        const int k0 = kt * 25;
        #pragma unroll
        for (int i = 0; i < 8; i++) {
            int e = tid + i * 200;
            int row = e / 25;
            int kk = e % 25;
            int gr = r0 + row;
            a_s[kk][row] = (gr < nRows) ? A[(long long)gr * K + k0 + kk] : 0.0f;
        }
        #pragma unroll
        for (int kk = 0; kk < 25; kk++)
            w_s[kk][tid] = W[(k0 + kk) * 200 + tid];
        __syncthreads();

        #pragma unroll
        for (int kk = 0; kk < 25; kk++) {
            float4 a0 = *(const float4*)&a_s[kk][ty * 8];
            float4 a1 = *(const float4*)&a_s[kk][ty * 8 + 4];
            ulonglong2 w01 = *(const ulonglong2*)&w_s[kk][tx * 8];
            ulonglong2 w23 = *(const ulonglong2*)&w_s[kk][tx * 8 + 4];
            unsigned long long av[8];
            av[0] = pack2(a0.x); av[1] = pack2(a0.y);
            av[2] = pack2(a0.z); av[3] = pack2(a0.w);
            av[4] = pack2(a1.x); av[5] = pack2(a1.y);
            av[6] = pack2(a1.z); av[7] = pack2(a1.w);
            #pragma unroll
            for (int r = 0; r < 8; r++) {
                acc[r][0] = fma2(av[r], w01.x, acc[r][0]);
                acc[r][1] = fma2(av[r], w01.y, acc[r][1]);
                acc[r][2] = fma2(av[r], w23.x, acc[r][2]);
                acc[r][3] = fma2(av[r], w23.y, acc[r][3]);
            }
        }
        __syncthreads();
    }

    #pragma unroll
    for (int r = 0; r < 8; r++) {
        int gr = r0 + ty * 8 + r;
        if (gr < nRows) {
            float o[8];
            *(ulonglong2*)&o[0] = make_ulonglong2(acc[r][0], acc[r][1]);
            *(ulonglong2*)&o[4] = make_ulonglong2(acc[r][2], acc[r][3]);
            if (LEAKY) {
                #pragma unroll
                for (int c = 0; c < 8; c++)
                    o[c] = o[c] > 0.f ? o[c] : ALPHA * o[c];
            }
            *(float4*)&C[(long long)gr * 200 + tx * 8]     = *(float4*)&o[0];
            *(float4*)&C[(long long)gr * 200 + tx * 8 + 4] = *(float4*)&o[4];
        }
    }
}

// ---------------- agg2: leaky + L2-normalize, 4 rows/block (64 thr/row) ----
__global__ void __launch_bounds__(256)
agg2_kernel(const float4* __restrict__ h, float* __restrict__ out, int nRows) {
    __shared__ float sred[4][2];
    const int g = threadIdx.x >> 6;        // row group 0..3
    const int t = threadIdx.x & 63;        // 0..63, 50 active
    const int r = blockIdx.x * 4 + g;
    const bool rowok = r < nRows;
    const bool act = rowok && (t < 50);
    const int beg = rowok ? g_starts[r] : 0;
    const int end = rowok ? g_starts[r + 1] : 0;

    float4 acc = make_float4(0.f, 0.f, 0.f, 0.f);
    int i = beg;
    for (; i + 3 < end; i += 4) {
        int s0 = __ldg(&g_src[i]),     s1 = __ldg(&g_src[i + 1]);
        int s2 = __ldg(&g_src[i + 2]), s3 = __ldg(&g_src[i + 3]);
        float v0 = __ldg(&g_val[i]),     v1 = __ldg(&g_val[i + 1]);
        float v2 = __ldg(&g_val[i + 2]), v3 = __ldg(&g_val[i + 3]);
        if (act) {
            float4 x0 = __ldg(&h[(long long)s0 * 50 + t]);
            float4 x1 = __ldg(&h[(long long)s1 * 50 + t]);
            float4 x2 = __ldg(&h[(long long)s2 * 50 + t]);
            float4 x3 = __ldg(&h[(long long)s3 * 50 + t]);
            acc.x = fmaf(x0.x, v0, acc.x); acc.y = fmaf(x0.y, v0, acc.y);
            acc.z = fmaf(x0.z, v0, acc.z); acc.w = fmaf(x0.w, v0, acc.w);
            acc.x = fmaf(x1.x, v1, acc.x); acc.y = fmaf(x1.y, v1, acc.y);
            acc.z = fmaf(x1.z, v1, acc.z); acc.w = fmaf(x1.w, v1, acc.w);
            acc.x = fmaf(x2.x, v2, acc.x); acc.y = fmaf(x2.y, v2, acc.y);
            acc.z = fmaf(x2.z, v2, acc.z); acc.w = fmaf(x2.w, v2, acc.w);
            acc.x = fmaf(x3.x, v3, acc.x); acc.y = fmaf(x3.y, v3, acc.y);
            acc.z = fmaf(x3.z, v3, acc.z); acc.w = fmaf(x3.w, v3, acc.w);
        }
    }
    for (; i < end; i++) {
        int s0 = __ldg(&g_src[i]);
        float v0 = __ldg(&g_val[i]);
        if (act) {
            float4 x0 = __ldg(&h[(long long)s0 * 50 + t]);
            acc.x = fmaf(x0.x, v0, acc.x); acc.y = fmaf(x0.y, v0, acc.y);
            acc.z = fmaf(x0.z, v0, acc.z); acc.w = fmaf(x0.w, v0, acc.w);
        }
    }
    acc.x = acc.x > 0.f ? acc.x : ALPHA * acc.x;
    acc.y = acc.y > 0.f ? acc.y : ALPHA * acc.y;
    acc.z = acc.z > 0.f ? acc.z : ALPHA * acc.z;
    acc.w = acc.w > 0.f ? acc.w : ALPHA * acc.w;

    float ss = act ? (acc.x * acc.x + acc.y * acc.y +
                      acc.z * acc.z + acc.w * acc.w) : 0.f;
    #pragma unroll
    for (int o = 16; o; o >>= 1) ss += __shfl_down_sync(0xffffffffu, ss, o);
    if ((threadIdx.x & 31) == 0) sred[g][(t >> 5)] = ss;
    __syncthreads();
    float inv = 1.0f / fmaxf(sqrtf(sred[g][0] + sred[g][1]), EPSN);
    acc.x *= inv; acc.y *= inv; acc.z *= inv; acc.w *= inv;
    if (act) ((float4*)out)[(long long)r * 50 + t] = acc;
}

// ---------------- launch ----------------
extern "C" void kernel_launch(void* const* d_in, const int* in_sizes, int n_in,
                              void* d_out, int out_size) {
    const float* emb = (const float*)d_in[0];        // [N_TOT, 100]
    const float* W1  = (const float*)d_in[1];        // [100, 200]
    const float* W2  = (const float*)d_in[2];        // [200, 200]
    const void*  ei  = d_in[3];                      // [2, E]
    const float* ev  = (const float*)d_in[4];        // [E]
    float* out = (float*)d_out;                      // [N_TOT, 200]

    float* buf0; cudaGetSymbolAddress((void**)&buf0, g_buf0);
    float* h1;   cudaGetSymbolAddress((void**)&h1, g_h1);

    // CSR build
    init_kernel<<<(N_TOT + 255) / 256, 256>>>((const int*)ei);
    hist_kernel<<<(E_NUM + 255) / 256, 256>>>(ei);
    scan1_kernel<<<SCAN_NB, SCAN_BLK>>>();
    scan2_kernel<<<SCAN_NB, SCAN_BLK>>>();
    scatter_kernel<<<(E_NUM + 255) / 256, 256>>>(ei, ev);

    dim3 gblock(25, 8);
    int ggrid = (N_TOT + 63) / 64;

    // Layer 1: agg(raw emb) -> gemm(+leaky)   [linearity: agg(X)@W == agg(X@W)]
    agg1_kernel<<<(N_TOT + 7) / 8, 256>>>((const float4*)emb, (float4*)buf0, N_TOT);
    gemm_kernel<D_IN, true><<<ggrid, gblock>>>(buf0, W1, h1, N_TOT);

    // Layer 2: gemm -> agg(+leaky+norm) -> out
    gemm_kernel<D_OUT, false><<<ggrid, gblock>>>(h1, W2, buf0, N_TOT);
    agg2_kernel<<<(N_TOT + 3) / 4, 256>>>((const float4*)buf0, out, N_TOT);
}

// round 3
// speedup vs baseline: 1.0945x; 1.0050x over previous
#include <cuda_runtime.h>
#include <cuda_bf16.h>
#include <cstdint>

#define N_ENT 50000
#define N_REL 500
#define N_TOT (N_ENT + N_REL)   // 50500
#define E_NUM 800000
#define D_IN  100
#define D_OUT 200
#define ALPHA 0.2f
#define EPSN  1e-12f

#define SCAN_BLK 1024
#define SCAN_NB  ((N_TOT + SCAN_BLK - 1) / SCAN_BLK)   // 50

// ---------------- scratch (device globals; zero-initialized at load) -------
__device__ float g_buf0[N_TOT * D_OUT];   // agg1 out [N,100] / gemm2 out [N,200]
__device__ float g_h1[N_TOT * D_OUT];     // layer-1 output [N,200]
__device__ int   g_counts[N_TOT];         // zeroed at load; re-zeroed by scan
__device__ int   g_starts[N_TOT + 1];
__device__ int   g_cursor[N_TOT];
__device__ int   g_bsum[SCAN_NB];
__device__ int   g_flag[SCAN_NB];         // lookback flags; reset by scatter
__device__ int2  g_edge[E_NUM];           // dst-sorted (src, val_bits)

// ---------------- helpers ----------------
__device__ __forceinline__ unsigned long long fma2(unsigned long long a,
                                                   unsigned long long b,
                                                   unsigned long long c) {
    unsigned long long d;
    asm("fma.rn.f32x2 %0, %1, %2, %3;" : "=l"(d) : "l"(a), "l"(b), "l"(c));
    return d;
}
__device__ __forceinline__ unsigned long long pack2(float x) {
    unsigned long long d;
    asm("mov.b64 %0, {%1, %1};" : "=l"(d) : "f"(x));
    return d;
}
__device__ __forceinline__ int load_idx(const void* ei, long long i, int is64) {
    if (is64) return (int)(((const long long*)ei)[i]);
    return ((const int*)ei)[i];
}
// Per-block int64-vs-int32 detection: for int64 little-endian indices < 50500,
// every odd 32-bit word of the first 256 is zero; int32 dst values make that
// probability ~0. Cheap (128 cached loads) and done redundantly per block.
__device__ __forceinline__ int detect_is64_block(const int* ei_words) {
    __shared__ int s_is64;
    if (threadIdx.x == 0) {
        int f = 1;
        #pragma unroll 8
        for (int j = 1; j < 256; j += 2)
            if (ei_words[j] != 0) f = 0;
        s_is64 = f;
    }
    __syncthreads();
    return s_is64;
}

// ---------------- hist: count edges per dst --------------------------------
__global__ void hist_kernel(const void* __restrict__ ei) {
    int is64 = detect_is64_block((const int*)ei);
    int e = blockIdx.x * blockDim.x + threadIdx.x;
    if (e < E_NUM) {
        int d = load_idx(ei, (long long)E_NUM + e, is64);
        atomicAdd(&g_counts[d], 1);
    }
}

// ---------------- single-pass scan with decoupled lookback -----------------
__global__ void __launch_bounds__(SCAN_BLK)
scan_kernel() {
    __shared__ int woff[32];
    __shared__ int s_off[2];
    const int tid = threadIdx.x;
    const int lane = tid & 31;
    const int wid = tid >> 5;
    const int b = blockIdx.x;
    const int i = b * SCAN_BLK + tid;

    int v = (i < N_TOT) ? g_counts[i] : 0;
    if (i < N_TOT) g_counts[i] = 0;        // re-zero for next replay

    // warp inclusive scan
    int incl = v;
    #pragma unroll
    for (int o = 1; o < 32; o <<= 1) {
        int t = __shfl_up_sync(0xffffffffu, incl, o);
        if (lane >= o) incl += t;
    }
    if (lane == 31) woff[wid] = incl;
    __syncthreads();
    if (wid == 0) {
        int w = woff[lane];
        int wincl = w;
        #pragma unroll
        for (int o = 1; o < 32; o <<= 1) {
            int t = __shfl_up_sync(0xffffffffu, wincl, o);
            if (lane >= o) wincl += t;
        }
        woff[lane] = wincl - w;            // exclusive warp offset
        if (lane == 31) {                  // publish block sum
            g_bsum[b] = wincl;
            __threadfence();
            atomicExch(&g_flag[b], 1);
        }
    }
    __syncthreads();

    // lookback: 2 warps gather sums of predecessor blocks (b <= 49 < 64)
    if (tid < 64) {
        int offv = 0;
        if (tid < b) {
            while (atomicAdd(&g_flag[tid], 0) == 0) { }
            __threadfence();
            offv = g_bsum[tid];
        }
        #pragma unroll
        for (int o = 16; o; o >>= 1) offv += __shfl_down_sync(0xffffffffu, offv, o);
        if ((tid & 31) == 0) s_off[tid >> 5] = offv;
    }
    __syncthreads();
    int off = s_off[0] + s_off[1];

    if (i < N_TOT) {
        int s = off + woff[wid] + (incl - v);
        g_starts[i] = s;
        g_cursor[i] = s;
    }
    if (b == SCAN_NB - 1 && tid == 0) {
        int tot = off;
        // s_off already includes blocks < b; add own block total
        tot += g_bsum[b];
        g_starts[N_TOT] = tot;
    }
}

// ---------------- scatter: build dst-sorted packed edge list ---------------
__global__ void scatter_kernel(const void* __restrict__ ei,
                               const float* __restrict__ ev) {
    int is64 = detect_is64_block((const int*)ei);
    int e = blockIdx.x * blockDim.x + threadIdx.x;
    // reset lookback flags for next replay (scan is complete by stream order)
    if (blockIdx.x == 0 && threadIdx.x < SCAN_NB) g_flag[threadIdx.x] = 0;
    if (e < E_NUM) {
        int s = load_idx(ei, e, is64);
        int d = load_idx(ei, (long long)E_NUM + e, is64);
        int pos = atomicAdd(&g_cursor[d], 1);
        g_edge[pos] = make_int2(s, __float_as_int(ev[e]));
    }
}

// ---------------- agg1: t1[r,0:100] = sum emb[src]*val ---------------------
// 8 warps/block, one row per warp; lanes 0..24 carry one float4 each.
__global__ void __launch_bounds__(256)
agg1_kernel(const float4* __restrict__ h, float4* __restrict__ out, int nRows) {
    const int g = threadIdx.x >> 5;
    const int lane = threadIdx.x & 31;
    const int r = blockIdx.x * 8 + g;
    if (r >= nRows) return;
    const bool act = lane < 25;
    const int beg = g_starts[r];
    const int end = g_starts[r + 1];

    float4 acc = make_float4(0.f, 0.f, 0.f, 0.f);
    int i = beg;
    for (; i + 3 < end; i += 4) {
        int2 e0 = __ldg(&g_edge[i]),     e1 = __ldg(&g_edge[i + 1]);
        int2 e2 = __ldg(&g_edge[i + 2]), e3 = __ldg(&g_edge[i + 3]);
        if (act) {
            float4 x0 = __ldg(&h[(long long)e0.x * 25 + lane]);
            float4 x1 = __ldg(&h[(long long)e1.x * 25 + lane]);
            float4 x2 = __ldg(&h[(long long)e2.x * 25 + lane]);
            float4 x3 = __ldg(&h[(long long)e3.x * 25 + lane]);
            float v0 = __int_as_float(e0.y), v1 = __int_as_float(e1.y);
            float v2 = __int_as_float(e2.y), v3 = __int_as_float(e3.y);
            acc.x = fmaf(x0.x, v0, acc.x); acc.y = fmaf(x0.y, v0, acc.y);
            acc.z = fmaf(x0.z, v0, acc.z); acc.w = fmaf(x0.w, v0, acc.w);
            acc.x = fmaf(x1.x, v1, acc.x); acc.y = fmaf(x1.y, v1, acc.y);
            acc.z = fmaf(x1.z, v1, acc.z); acc.w = fmaf(x1.w, v1, acc.w);
            acc.x = fmaf(x2.x, v2, acc.x); acc.y = fmaf(x2.y, v2, acc.y);
            acc.z = fmaf(x2.z, v2, acc.z); acc.w = fmaf(x2.w, v2, acc.w);
            acc.x = fmaf(x3.x, v3, acc.x); acc.y = fmaf(x3.y, v3, acc.y);
            acc.z = fmaf(x3.z, v3, acc.z); acc.w = fmaf(x3.w, v3, acc.w);
        }
    }
    for (; i < end; i++) {
        int2 e0 = __ldg(&g_edge[i]);
        if (act) {
            float v0 = __int_as_float(e0.y);
            float4 x0 = __ldg(&h[(long long)e0.x * 25 + lane]);
            acc.x = fmaf(x0.x, v0, acc.x); acc.y = fmaf(x0.y, v0, acc.y);
            acc.z = fmaf(x0.z, v0, acc.z); acc.w = fmaf(x0.w, v0, acc.w);
        }
    }
    if (act) out[(long long)r * 25 + lane] = acc;
}

// ---------------- GEMM: C[N,200] = act( A[N,K] * W[K,200] ) ----------------
template <int K, bool LEAKY>
__global__ void __launch_bounds__(200)
gemm_kernel(const float* __restrict__ A, const float* __restrict__ W,
            float* __restrict__ C, int nRows) {
    __shared__ float a_s[25][64];
    __shared__ float w_s[25][200];
    const int tx = threadIdx.x;
    const int ty = threadIdx.y;
    const int tid = ty * 25 + tx;
    const int r0 = blockIdx.x * 64;

    unsigned long long acc[8][4];
    #pragma unroll
    for (int r = 0; r < 8; r++)
        #pragma unroll
        for (int c = 0; c < 4; c++) acc[r][c] = 0ull;

    #pragma unroll
    for (int kt = 0; kt < K / 25; kt++) {
        const int k0 = kt * 25;
        #pragma unroll
        for (int i = 0; i < 8; i++) {
            int e = tid + i * 200;
            int row = e / 25;
            int kk = e % 25;
            int gr = r0 + row;
            a_s[kk][row] = (gr < nRows) ? A[(long long)gr * K + k0 + kk] : 0.0f;
        }
        #pragma unroll
        for (int kk = 0; kk < 25; kk++)
            w_s[kk][tid] = W[(k0 + kk) * 200 + tid];
        __syncthreads();

        #pragma unroll
        for (int kk = 0; kk < 25; kk++) {
            float4 a0 = *(const float4*)&a_s[kk][ty * 8];
            float4 a1 = *(const float4*)&a_s[kk][ty * 8 + 4];
            ulonglong2 w01 = *(const ulonglong2*)&w_s[kk][tx * 8];
            ulonglong2 w23 = *(const ulonglong2*)&w_s[kk][tx * 8 + 4];
            unsigned long long av[8];
            av[0] = pack2(a0.x); av[1] = pack2(a0.y);
            av[2] = pack2(a0.z); av[3] = pack2(a0.w);
            av[4] = pack2(a1.x); av[5] = pack2(a1.y);
            av[6] = pack2(a1.z); av[7] = pack2(a1.w);
            #pragma unroll
            for (int r = 0; r < 8; r++) {
                acc[r][0] = fma2(av[r], w01.x, acc[r][0]);
                acc[r][1] = fma2(av[r], w01.y, acc[r][1]);
                acc[r][2] = fma2(av[r], w23.x, acc[r][2]);
                acc[r][3] = fma2(av[r], w23.y, acc[r][3]);
            }
        }
        __syncthreads();
    }

    #pragma unroll
    for (int r = 0; r < 8; r++) {
        int gr = r0 + ty * 8 + r;
        if (gr < nRows) {
            float o[8];
            *(ulonglong2*)&o[0] = make_ulonglong2(acc[r][0], acc[r][1]);
            *(ulonglong2*)&o[4] = make_ulonglong2(acc[r][2], acc[r][3]);
            if (LEAKY) {
                #pragma unroll
                for (int c = 0; c < 8; c++)
                    o[c] = o[c] > 0.f ? o[c] : ALPHA * o[c];
            }
            *(float4*)&C[(long long)gr * 200 + tx * 8]     = *(float4*)&o[0];
            *(float4*)&C[(long long)gr * 200 + tx * 8 + 4] = *(float4*)&o[4];
        }
    }
}

// ---------------- agg2: leaky + L2-normalize, 4 rows/block (64 thr/row) ----
__global__ void __launch_bounds__(256)
agg2_kernel(const float4* __restrict__ h, float* __restrict__ out, int nRows) {
    __shared__ float sred[4][2];
    const int g = threadIdx.x >> 6;
    const int t = threadIdx.x & 63;
    const int r = blockIdx.x * 4 + g;
    const bool rowok = r < nRows;
    const bool act = rowok && (t < 50);
    const int beg = rowok ? g_starts[r] : 0;
    const int end = rowok ? g_starts[r + 1] : 0;

    float4 acc = make_float4(0.f, 0.f, 0.f, 0.f);
    int i = beg;
    for (; i + 3 < end; i += 4) {
        int2 e0 = __ldg(&g_edge[i]),     e1 = __ldg(&g_edge[i + 1]);
        int2 e2 = __ldg(&g_edge[i + 2]), e3 = __ldg(&g_edge[i + 3]);
        if (act) {
            float4 x0 = __ldg(&h[(long long)e0.x * 50 + t]);
            float4 x1 = __ldg(&h[(long long)e1.x * 50 + t]);
            float4 x2 = __ldg(&h[(long long)e2.x * 50 + t]);
            float4 x3 = __ldg(&h[(long long)e3.x * 50 + t]);
            float v0 = __int_as_float(e0.y), v1 = __int_as_float(e1.y);
            float v2 = __int_as_float(e2.y), v3 = __int_as_float(e3.y);
            acc.x = fmaf(x0.x, v0, acc.x); acc.y = fmaf(x0.y, v0, acc.y);
            acc.z = fmaf(x0.z, v0, acc.z); acc.w = fmaf(x0.w, v0, acc.w);
            acc.x = fmaf(x1.x, v1, acc.x); acc.y = fmaf(x1.y, v1, acc.y);
            acc.z = fmaf(x1.z, v1, acc.z); acc.w = fmaf(x1.w, v1, acc.w);
            acc.x = fmaf(x2.x, v2, acc.x); acc.y = fmaf(x2.y, v2, acc.y);
            acc.z = fmaf(x2.z, v2, acc.z); acc.w = fmaf(x2.w, v2, acc.w);
            acc.x = fmaf(x3.x, v3, acc.x); acc.y = fmaf(x3.y, v3, acc.y);
            acc.z = fmaf(x3.z, v3, acc.z); acc.w = fmaf(x3.w, v3, acc.w);
        }
    }
    for (; i < end; i++) {
        int2 e0 = __ldg(&g_edge[i]);
        if (act) {
            float v0 = __int_as_float(e0.y);
            float4 x0 = __ldg(&h[(long long)e0.x * 50 + t]);
            acc.x = fmaf(x0.x, v0, acc.x); acc.y = fmaf(x0.y, v0, acc.y);
            acc.z = fmaf(x0.z, v0, acc.z); acc.w = fmaf(x0.w, v0, acc.w);
        }
    }
    acc.x = acc.x > 0.f ? acc.x : ALPHA * acc.x;
    acc.y = acc.y > 0.f ? acc.y : ALPHA * acc.y;
    acc.z = acc.z > 0.f ? acc.z : ALPHA * acc.z;
    acc.w = acc.w > 0.f ? acc.w : ALPHA * acc.w;

    float ss = act ? (acc.x * acc.x + acc.y * acc.y +
                      acc.z * acc.z + acc.w * acc.w) : 0.f;
    #pragma unroll
    for (int o = 16; o; o >>= 1) ss += __shfl_down_sync(0xffffffffu, ss, o);
    if ((threadIdx.x & 31) == 0) sred[g][(t >> 5)] = ss;
    __syncthreads();
    float inv = 1.0f / fmaxf(sqrtf(sred[g][0] + sred[g][1]), EPSN);
    acc.x *= inv; acc.y *= inv; acc.z *= inv; acc.w *= inv;
    if (act) ((float4*)out)[(long long)r * 50 + t] = acc;
}

// ---------------- launch ----------------
extern "C" void kernel_launch(void* const* d_in, const int* in_sizes, int n_in,
                              void* d_out, int out_size) {
    const float* emb = (const float*)d_in[0];        // [N_TOT, 100]
    const float* W1  = (const float*)d_in[1];        // [100, 200]
    const float* W2  = (const float*)d_in[2];        // [200, 200]
    const void*  ei  = d_in[3];                      // [2, E]
    const float* ev  = (const float*)d_in[4];        // [E]
    float* out = (float*)d_out;                      // [N_TOT, 200]

    float* buf0; cudaGetSymbolAddress((void**)&buf0, g_buf0);
    float* h1;   cudaGetSymbolAddress((void**)&h1, g_h1);

    // CSR build (3 launches)
    hist_kernel<<<(E_NUM + 255) / 256, 256>>>(ei);
    scan_kernel<<<SCAN_NB, SCAN_BLK>>>();
    scatter_kernel<<<(E_NUM + 255) / 256, 256>>>(ei, ev);

    dim3 gblock(25, 8);
    int ggrid = (N_TOT + 63) / 64;

    // Layer 1: agg(raw emb) -> gemm(+leaky)   [linearity]
    agg1_kernel<<<(N_TOT + 7) / 8, 256>>>((const float4*)emb, (float4*)buf0, N_TOT);
    gemm_kernel<D_IN, true><<<ggrid, gblock>>>(buf0, W1, h1, N_TOT);

    // Layer 2: gemm -> agg(+leaky+norm) -> out
    gemm_kernel<D_OUT, false><<<ggrid, gblock>>>(h1, W2, buf0, N_TOT);
    agg2_kernel<<<(N_TOT + 3) / 4, 256>>>((const float4*)buf0, out, N_TOT);
}

// round 4
// speedup vs baseline: 2.0296x; 1.8544x over previous
#include <cuda_runtime.h>
#include <cuda_bf16.h>
#include <cstdint>

#define N_ENT 50000
#define N_REL 500
#define N_TOT (N_ENT + N_REL)   // 50500
#define E_NUM 800000
#define D_IN  100
#define D_OUT 200
#define ALPHA 0.2f
#define EPSN  1e-12f

#define SCAN_BLK 1024
#define SCAN_NB  ((N_TOT + SCAN_BLK - 1) / SCAN_BLK)   // 50

// ---------------- scratch (device globals; zero-initialized at load) -------
__device__ float g_buf0[N_TOT * D_OUT];   // agg1 out [N,100] / gemm2 out [N,200]
__device__ float g_h1[N_TOT * D_OUT];     // layer-1 output [N,200]
__device__ int   g_counts[N_TOT];         // zeroed at load; re-zeroed by scan
__device__ int   g_starts[N_TOT + 1];
__device__ int   g_cursor[N_TOT];
__device__ int   g_bsum[SCAN_NB];
__device__ int   g_flag[SCAN_NB];         // lookback flags; reset by reset_kernel
__device__ int2  g_edge[E_NUM];           // dst-sorted (src, val_bits)

// ---------------- helpers ----------------
__device__ __forceinline__ int load_idx(const void* ei, long long i, int is64) {
    if (is64) return (int)(((const long long*)ei)[i]);
    return ((const int*)ei)[i];
}
__device__ __forceinline__ int detect_is64_block(const int* ei_words) {
    __shared__ int s_is64;
    if (threadIdx.x == 0) {
        int f = 1;
        #pragma unroll 8
        for (int j = 1; j < 256; j += 2)
            if (ei_words[j] != 0) f = 0;
        s_is64 = f;
    }
    __syncthreads();
    return s_is64;
}
__device__ __forceinline__ unsigned tf32_of(float x) {
    unsigned r;
    asm("cvt.rna.tf32.f32 %0, %1;" : "=r"(r) : "f"(x));
    return r;
}
__device__ __forceinline__ void mma_tf32(float& d0, float& d1, float& d2, float& d3,
                                         unsigned a0, unsigned a1, unsigned a2, unsigned a3,
                                         unsigned b0, unsigned b1,
                                         float c0, float c1, float c2, float c3) {
    asm("mma.sync.aligned.m16n8k8.row.col.f32.tf32.tf32.f32 "
        "{%0,%1,%2,%3},{%4,%5,%6,%7},{%8,%9},{%10,%11,%12,%13};"
        : "=f"(d0), "=f"(d1), "=f"(d2), "=f"(d3)
        : "r"(a0), "r"(a1), "r"(a2), "r"(a3), "r"(b0), "r"(b1),
          "f"(c0), "f"(c1), "f"(c2), "f"(c3));
}

// ---------------- reset: clear lookback flags (also shifts ncu window) -----
__global__ void reset_kernel() {
    if (threadIdx.x < SCAN_NB) g_flag[threadIdx.x] = 0;
}

// ---------------- hist ----------------
__global__ void hist_kernel(const void* __restrict__ ei) {
    int is64 = detect_is64_block((const int*)ei);
    int e = blockIdx.x * blockDim.x + threadIdx.x;
    if (e < E_NUM) {
        int d = load_idx(ei, (long long)E_NUM + e, is64);
        atomicAdd(&g_counts[d], 1);
    }
}

// ---------------- single-pass scan with decoupled lookback -----------------
__global__ void __launch_bounds__(SCAN_BLK)
scan_kernel() {
    __shared__ int woff[32];
    __shared__ int s_off[2];
    const int tid = threadIdx.x;
    const int lane = tid & 31;
    const int wid = tid >> 5;
    const int b = blockIdx.x;
    const int i = b * SCAN_BLK + tid;

    int v = (i < N_TOT) ? g_counts[i] : 0;
    if (i < N_TOT) g_counts[i] = 0;        // re-zero for next replay

    int incl = v;
    #pragma unroll
    for (int o = 1; o < 32; o <<= 1) {
        int t = __shfl_up_sync(0xffffffffu, incl, o);
        if (lane >= o) incl += t;
    }
    if (lane == 31) woff[wid] = incl;
    __syncthreads();
    if (wid == 0) {
        int w = woff[lane];
        int wincl = w;
        #pragma unroll
        for (int o = 1; o < 32; o <<= 1) {
            int t = __shfl_up_sync(0xffffffffu, wincl, o);
            if (lane >= o) wincl += t;
        }
        woff[lane] = wincl - w;
        if (lane == 31) {
            g_bsum[b] = wincl;
            __threadfence();
            atomicExch(&g_flag[b], 1);
        }
    }
    __syncthreads();

    if (tid < 64) {
        int offv = 0;
        if (tid < b) {
            while (atomicAdd(&g_flag[tid], 0) == 0) { }
            __threadfence();
            offv = g_bsum[tid];
        }
        #pragma unroll
        for (int o = 16; o; o >>= 1) offv += __shfl_down_sync(0xffffffffu, offv, o);
        if ((tid & 31) == 0) s_off[tid >> 5] = offv;
    }
    __syncthreads();
    int off = s_off[0] + s_off[1];

    if (i < N_TOT) {
        int s = off + woff[wid] + (incl - v);
        g_starts[i] = s;
        g_cursor[i] = s;
    }
    if (b == SCAN_NB - 1 && tid == 0)
        g_starts[N_TOT] = off + g_bsum[b];
}

// ---------------- scatter: build dst-sorted packed edge list ---------------
__global__ void scatter_kernel(const void* __restrict__ ei,
                               const float* __restrict__ ev) {
    int is64 = detect_is64_block((const int*)ei);
    int e = blockIdx.x * blockDim.x + threadIdx.x;
    if (e < E_NUM) {
        int s = load_idx(ei, e, is64);
        int d = load_idx(ei, (long long)E_NUM + e, is64);
        int pos = atomicAdd(&g_cursor[d], 1);
        g_edge[pos] = make_int2(s, __float_as_int(ev[e]));
    }
}

// ---------------- agg1: t1[r,0:100] = sum emb[src]*val ---------------------
__global__ void __launch_bounds__(256)
agg1_kernel(const float4* __restrict__ h, float4* __restrict__ out, int nRows) {
    const int g = threadIdx.x >> 5;
    const int lane = threadIdx.x & 31;
    const int r = blockIdx.x * 8 + g;
    if (r >= nRows) return;
    const bool act = lane < 25;
    const int beg = g_starts[r];
    const int end = g_starts[r + 1];

    float4 acc = make_float4(0.f, 0.f, 0.f, 0.f);
    int i = beg;
    for (; i + 3 < end; i += 4) {
        int2 e0 = __ldg(&g_edge[i]),     e1 = __ldg(&g_edge[i + 1]);
        int2 e2 = __ldg(&g_edge[i + 2]), e3 = __ldg(&g_edge[i + 3]);
        if (act) {
            float4 x0 = __ldg(&h[(long long)e0.x * 25 + lane]);
            float4 x1 = __ldg(&h[(long long)e1.x * 25 + lane]);
            float4 x2 = __ldg(&h[(long long)e2.x * 25 + lane]);
            float4 x3 = __ldg(&h[(long long)e3.x * 25 + lane]);
            float v0 = __int_as_float(e0.y), v1 = __int_as_float(e1.y);
            float v2 = __int_as_float(e2.y), v3 = __int_as_float(e3.y);
            acc.x = fmaf(x0.x, v0, acc.x); acc.y = fmaf(x0.y, v0, acc.y);
            acc.z = fmaf(x0.z, v0, acc.z); acc.w = fmaf(x0.w, v0, acc.w);
            acc.x = fmaf(x1.x, v1, acc.x); acc.y = fmaf(x1.y, v1, acc.y);
            acc.z = fmaf(x1.z, v1, acc.z); acc.w = fmaf(x1.w, v1, acc.w);
            acc.x = fmaf(x2.x, v2, acc.x); acc.y = fmaf(x2.y, v2, acc.y);
            acc.z = fmaf(x2.z, v2, acc.z); acc.w = fmaf(x2.w, v2, acc.w);
            acc.x = fmaf(x3.x, v3, acc.x); acc.y = fmaf(x3.y, v3, acc.y);
            acc.z = fmaf(x3.z, v3, acc.z); acc.w = fmaf(x3.w, v3, acc.w);
        }
    }
    for (; i < end; i++) {
        int2 e0 = __ldg(&g_edge[i]);
        if (act) {
            float v0 = __int_as_float(e0.y);
            float4 x0 = __ldg(&h[(long long)e0.x * 25 + lane]);
            acc.x = fmaf(x0.x, v0, acc.x); acc.y = fmaf(x0.y, v0, acc.y);
            acc.z = fmaf(x0.z, v0, acc.z); acc.w = fmaf(x0.w, v0, acc.w);
        }
    }
    if (act) out[(long long)r * 25 + lane] = acc;
}

// ---------------- tf32 HMMA GEMM: C[N,200] = act(A[N,K] @ W[K,200]) --------
// Block 256 thr = 8 warps (4 over M=64, 2 over N: 13+12 n8-tiles).
// K staged in chunks of 40 (5 k-steps of 8), converted to tf32 on store.
#define CK 40
template <int K, int KP, bool LEAKY>
__global__ void __launch_bounds__(256)
gemm_tf32_kernel(const float* __restrict__ A, const float* __restrict__ W,
                 float* __restrict__ C, int nRows) {
    __shared__ unsigned a_s[64][44];        // padded rows (44) for bank spread
    __shared__ unsigned w_s[CK][200];
    const int tid = threadIdx.x;
    const int wid = tid >> 5;
    const int lane = tid & 31;
    const int grp = lane >> 2;              // 0..7
    const int tig = lane & 3;               // 0..3
    const int wm = wid & 3;                 // m-tile: rows wm*16
    const int wn = wid >> 2;                // n-half
    const int jbase = wn ? 13 : 0;
    const int jcount = wn ? 12 : 13;
    const int r0 = blockIdx.x * 64;

    float acc[13][4];
    #pragma unroll
    for (int j = 0; j < 13; j++)
        #pragma unroll
        for (int c = 0; c < 4; c++) acc[j][c] = 0.f;

    #pragma unroll
    for (int ch = 0; ch < KP / CK; ch++) {
        const int k0 = ch * CK;
        // stage A chunk: 64 rows x 40 k  (640 float4 loads across 256 threads)
        #pragma unroll
        for (int i = 0; i < 3; i++) {
            int idx4 = tid + i * 256;
            if (idx4 < 640) {
                int row = idx4 / 10;
                int q = idx4 % 10;
                int gr = r0 + row;
                float4 v = make_float4(0.f, 0.f, 0.f, 0.f);
                if (gr < nRows && k0 + q * 4 < K)
                    v = *(const float4*)&A[(long long)gr * K + k0 + q * 4];
                a_s[row][q * 4 + 0] = tf32_of(v.x);
                a_s[row][q * 4 + 1] = tf32_of(v.y);
                a_s[row][q * 4 + 2] = tf32_of(v.z);
                a_s[row][q * 4 + 3] = tf32_of(v.w);
            }
        }
        // stage W chunk: 40 k x 200 cols (2000 float4 loads)
        #pragma unroll
        for (int i = 0; i < 8; i++) {
            int idx4 = tid + i * 256;
            if (idx4 < 2000) {
                int kk = idx4 / 50;
                int c4 = idx4 % 50;
                float4 v = make_float4(0.f, 0.f, 0.f, 0.f);
                if (k0 + kk < K)
                    v = *(const float4*)&W[(k0 + kk) * 200 + c4 * 4];
                w_s[kk][c4 * 4 + 0] = tf32_of(v.x);
                w_s[kk][c4 * 4 + 1] = tf32_of(v.y);
                w_s[kk][c4 * 4 + 2] = tf32_of(v.z);
                w_s[kk][c4 * 4 + 3] = tf32_of(v.w);
            }
        }
        __syncthreads();

        #pragma unroll
        for (int ks = 0; ks < CK / 8; ks++) {
            const int kk = ks * 8;
            unsigned a0 = a_s[wm * 16 + grp][kk + tig];
            unsigned a1 = a_s[wm * 16 + grp + 8][kk + tig];
            unsigned a2 = a_s[wm * 16 + grp][kk + tig + 4];
            unsigned a3 = a_s[wm * 16 + grp + 8][kk + tig + 4];
            #pragma unroll
            for (int j = 0; j < 13; j++) {
                if (j < jcount) {
                    int n0 = (jbase + j) * 8;
                    unsigned b0 = w_s[kk + tig][n0 + grp];
                    unsigned b1 = w_s[kk + tig + 4][n0 + grp];
                    mma_tf32(acc[j][0], acc[j][1], acc[j][2], acc[j][3],
                             a0, a1, a2, a3, b0, b1,
                             acc[j][0], acc[j][1], acc[j][2], acc[j][3]);
                }
            }
        }
        __syncthreads();
    }

    // store: c0,c1 at (row grp, cols 2t,2t+1); c2,c3 at row grp+8
    const int row_lo = r0 + wm * 16 + grp;
    const int row_hi = row_lo + 8;
    #pragma unroll
    for (int j = 0; j < 13; j++) {
        if (j < jcount) {
            int col = (jbase + j) * 8 + tig * 2;
            float o0 = acc[j][0], o1 = acc[j][1], o2 = acc[j][2], o3 = acc[j][3];
            if (LEAKY) {
                o0 = o0 > 0.f ? o0 : ALPHA * o0;
                o1 = o1 > 0.f ? o1 : ALPHA * o1;
                o2 = o2 > 0.f ? o2 : ALPHA * o2;
                o3 = o3 > 0.f ? o3 : ALPHA * o3;
            }
            if (row_lo < nRows) *(float2*)&C[(long long)row_lo * 200 + col] = make_float2(o0, o1);
            if (row_hi < nRows) *(float2*)&C[(long long)row_hi * 200 + col] = make_float2(o2, o3);
        }
    }
}

// ---------------- agg2: leaky + L2-normalize ------------------------------
__global__ void __launch_bounds__(256)
agg2_kernel(const float4* __restrict__ h, float* __restrict__ out, int nRows) {
    __shared__ float sred[4][2];
    const int g = threadIdx.x >> 6;
    const int t = threadIdx.x & 63;
    const int r = blockIdx.x * 4 + g;
    const bool rowok = r < nRows;
    const bool act = rowok && (t < 50);
    const int beg = rowok ? g_starts[r] : 0;
    const int end = rowok ? g_starts[r + 1] : 0;

    float4 acc = make_float4(0.f, 0.f, 0.f, 0.f);
    int i = beg;
    for (; i + 3 < end; i += 4) {
        int2 e0 = __ldg(&g_edge[i]),     e1 = __ldg(&g_edge[i + 1]);
        int2 e2 = __ldg(&g_edge[i + 2]), e3 = __ldg(&g_edge[i + 3]);
        if (act) {
            float4 x0 = __ldg(&h[(long long)e0.x * 50 + t]);
            float4 x1 = __ldg(&h[(long long)e1.x * 50 + t]);
            float4 x2 = __ldg(&h[(long long)e2.x * 50 + t]);
            float4 x3 = __ldg(&h[(long long)e3.x * 50 + t]);
            float v0 = __int_as_float(e0.y), v1 = __int_as_float(e1.y);
            float v2 = __int_as_float(e2.y), v3 = __int_as_float(e3.y);
            acc.x = fmaf(x0.x, v0, acc.x); acc.y = fmaf(x0.y, v0, acc.y);
            acc.z = fmaf(x0.z, v0, acc.z); acc.w = fmaf(x0.w, v0, acc.w);
            acc.x = fmaf(x1.x, v1, acc.x); acc.y = fmaf(x1.y, v1, acc.y);
            acc.z = fmaf(x1.z, v1, acc.z); acc.w = fmaf(x1.w, v1, acc.w);
            acc.x = fmaf(x2.x, v2, acc.x); acc.y = fmaf(x2.y, v2, acc.y);
            acc.z = fmaf(x2.z, v2, acc.z); acc.w = fmaf(x2.w, v2, acc.w);
            acc.x = fmaf(x3.x, v3, acc.x); acc.y = fmaf(x3.y, v3, acc.y);
            acc.z = fmaf(x3.z, v3, acc.z); acc.w = fmaf(x3.w, v3, acc.w);
        }
    }
    for (; i < end; i++) {
        int2 e0 = __ldg(&g_edge[i]);
        if (act) {
            float v0 = __int_as_float(e0.y);
            float4 x0 = __ldg(&h[(long long)e0.x * 50 + t]);
            acc.x = fmaf(x0.x, v0, acc.x); acc.y = fmaf(x0.y, v0, acc.y);
            acc.z = fmaf(x0.z, v0, acc.z); acc.w = fmaf(x0.w, v0, acc.w);
        }
    }
    acc.x = acc.x > 0.f ? acc.x : ALPHA * acc.x;
    acc.y = acc.y > 0.f ? acc.y : ALPHA * acc.y;
    acc.z = acc.z > 0.f ? acc.z : ALPHA * acc.z;
    acc.w = acc.w > 0.f ? acc.w : ALPHA * acc.w;

    float ss = act ? (acc.x * acc.x + acc.y * acc.y +
                      acc.z * acc.z + acc.w * acc.w) : 0.f;
    #pragma unroll
    for (int o = 16; o; o >>= 1) ss += __shfl_down_sync(0xffffffffu, ss, o);
    if ((threadIdx.x & 31) == 0) sred[g][(t >> 5)] = ss;
    __syncthreads();
    float inv = 1.0f / fmaxf(sqrtf(sred[g][0] + sred[g][1]), EPSN);
    acc.x *= inv; acc.y *= inv; acc.z *= inv; acc.w *= inv;
    if (act) ((float4*)out)[(long long)r * 50 + t] = acc;
}

// ---------------- launch ----------------
extern "C" void kernel_launch(void* const* d_in, const int* in_sizes, int n_in,
                              void* d_out, int out_size) {
    const float* emb = (const float*)d_in[0];        // [N_TOT, 100]
    const float* W1  = (const float*)d_in[1];        // [100, 200]
    const float* W2  = (const float*)d_in[2];        // [200, 200]
    const void*  ei  = d_in[3];                      // [2, E]
    const float* ev  = (const float*)d_in[4];        // [E]
    float* out = (float*)d_out;                      // [N_TOT, 200]

    float* buf0; cudaGetSymbolAddress((void**)&buf0, g_buf0);
    float* h1;   cudaGetSymbolAddress((void**)&h1, g_h1);

    // CSR build
    reset_kernel<<<1, 64>>>();
    hist_kernel<<<(E_NUM + 255) / 256, 256>>>(ei);
    scan_kernel<<<SCAN_NB, SCAN_BLK>>>();
    scatter_kernel<<<(E_NUM + 255) / 256, 256>>>(ei, ev);   // <- profiled (4th)

    int ggrid = (N_TOT + 63) / 64;

    // Layer 1: agg(raw emb) -> gemm(+leaky)   [linearity]
    agg1_kernel<<<(N_TOT + 7) / 8, 256>>>((const float4*)emb, (float4*)buf0, N_TOT);
    gemm_tf32_kernel<D_IN, 120, true><<<ggrid, 256>>>(buf0, W1, h1, N_TOT);

    // Layer 2: gemm -> agg(+leaky+norm) -> out
    gemm_tf32_kernel<D_OUT, 200, false><<<ggrid, 256>>>(h1, W2, buf0, N_TOT);
    agg2_kernel<<<(N_TOT + 3) / 4, 256>>>((const float4*)buf0, out, N_TOT);
}

// round 5
// speedup vs baseline: 2.1053x; 1.0373x over previous
#include <cuda_runtime.h>
#include <cuda_bf16.h>
#include <cstdint>

#define N_ENT 50000
#define N_REL 500
#define N_TOT (N_ENT + N_REL)   // 50500
#define E_NUM 800000
#define D_IN  100
#define D_OUT 200
#define ALPHA 0.2f
#define EPSN  1e-12f

#define SCAN_BLK 1024
#define SCAN_NB  ((N_TOT + SCAN_BLK - 1) / SCAN_BLK)   // 50

// ---------------- scratch (device globals; zero-initialized at load) -------
__device__ float g_buf0[N_TOT * D_OUT];   // agg1 out [N,100] / aggH out [N,200]
__device__ float g_h1[N_TOT * D_OUT];     // layer-1 output [N,200]
__device__ int   g_counts[N_TOT];         // zeroed at load; re-zeroed by scan
__device__ int   g_starts[N_TOT + 1];
__device__ int   g_cursor[N_TOT];
__device__ int   g_bsum[SCAN_NB];
__device__ int   g_flag[SCAN_NB];         // lookback flags; reset by hist blk0
__device__ int2  g_edge[E_NUM];           // dst-sorted (src, val_bits)

// ---------------- helpers ----------------
__device__ __forceinline__ int detect_is64_block(const int* ei_words) {
    __shared__ int s_is64;
    if (threadIdx.x == 0) {
        int f = 1;
        #pragma unroll 8
        for (int j = 1; j < 256; j += 2)
            if (ei_words[j] != 0) f = 0;
        s_is64 = f;
    }
    __syncthreads();
    return s_is64;
}
__device__ __forceinline__ unsigned tf32_of(float x) {
    unsigned r;
    asm("cvt.rna.tf32.f32 %0, %1;" : "=r"(r) : "f"(x));
    return r;
}
__device__ __forceinline__ void mma_tf32(float& d0, float& d1, float& d2, float& d3,
                                         unsigned a0, unsigned a1, unsigned a2, unsigned a3,
                                         unsigned b0, unsigned b1,
                                         float c0, float c1, float c2, float c3) {
    asm("mma.sync.aligned.m16n8k8.row.col.f32.tf32.tf32.f32 "
        "{%0,%1,%2,%3},{%4,%5,%6,%7},{%8,%9},{%10,%11,%12,%13};"
        : "=f"(d0), "=f"(d1), "=f"(d2), "=f"(d3)
        : "r"(a0), "r"(a1), "r"(a2), "r"(a3), "r"(b0), "r"(b1),
          "f"(c0), "f"(c1), "f"(c2), "f"(c3));
}
// load 4 consecutive edge indices starting at element base+4*e4 of ei
__device__ __forceinline__ void load_idx4(const void* ei, long long base, int e4,
                                          int is64, int d[4]) {
    if (is64) {
        const longlong2* p = (const longlong2*)ei;
        long long off = (base + 4LL * e4) >> 1;
        longlong2 a = __ldg(&p[off]);
        longlong2 b = __ldg(&p[off + 1]);
        d[0] = (int)a.x; d[1] = (int)a.y; d[2] = (int)b.x; d[3] = (int)b.y;
    } else {
        const int4* p = (const int4*)ei;
        int4 a = __ldg(&p[(base + 4LL * e4) >> 2]);
        d[0] = a.x; d[1] = a.y; d[2] = a.z; d[3] = a.w;
    }
}

// ---------------- hist: 4 edges/thread; block 0 resets lookback flags ------
__global__ void __launch_bounds__(256)
hist_kernel(const void* __restrict__ ei) {
    int is64 = detect_is64_block((const int*)ei);
    if (blockIdx.x == 0 && threadIdx.x < SCAN_NB) g_flag[threadIdx.x] = 0;
    int e4 = blockIdx.x * blockDim.x + threadIdx.x;
    if (e4 < E_NUM / 4) {
        int d[4];
        load_idx4(ei, E_NUM, e4, is64, d);
        atomicAdd(&g_counts[d[0]], 1);
        atomicAdd(&g_counts[d[1]], 1);
        atomicAdd(&g_counts[d[2]], 1);
        atomicAdd(&g_counts[d[3]], 1);
    }
}

// ---------------- single-pass scan with decoupled lookback -----------------
__global__ void __launch_bounds__(SCAN_BLK)
scan_kernel() {
    __shared__ int woff[32];
    __shared__ int s_off[2];
    const int tid = threadIdx.x;
    const int lane = tid & 31;
    const int wid = tid >> 5;
    const int b = blockIdx.x;
    const int i = b * SCAN_BLK + tid;

    int v = (i < N_TOT) ? g_counts[i] : 0;
    if (i < N_TOT) g_counts[i] = 0;        // re-zero for next replay

    int incl = v;
    #pragma unroll
    for (int o = 1; o < 32; o <<= 1) {
        int t = __shfl_up_sync(0xffffffffu, incl, o);
        if (lane >= o) incl += t;
    }
    if (lane == 31) woff[wid] = incl;
    __syncthreads();
    if (wid == 0) {
        int w = woff[lane];
        int wincl = w;
        #pragma unroll
        for (int o = 1; o < 32; o <<= 1) {
            int t = __shfl_up_sync(0xffffffffu, wincl, o);
            if (lane >= o) wincl += t;
        }
        woff[lane] = wincl - w;
        if (lane == 31) {
            g_bsum[b] = wincl;
            __threadfence();
            atomicExch(&g_flag[b], 1);
        }
    }
    __syncthreads();

    if (tid < 64) {
        int offv = 0;
        if (tid < b) {
            while (atomicAdd(&g_flag[tid], 0) == 0) { }
            __threadfence();
            offv = g_bsum[tid];
        }
        #pragma unroll
        for (int o = 16; o; o >>= 1) offv += __shfl_down_sync(0xffffffffu, offv, o);
        if ((tid & 31) == 0) s_off[tid >> 5] = offv;
    }
    __syncthreads();
    int off = s_off[0] + s_off[1];

    if (i < N_TOT) {
        int s = off + woff[wid] + (incl - v);
        g_starts[i] = s;
        g_cursor[i] = s;
    }
    if (b == SCAN_NB - 1 && tid == 0)
        g_starts[N_TOT] = off + g_bsum[b];
}

// ---------------- scatter: 4 edges/thread, packed STG.64 -------------------
__global__ void __launch_bounds__(256)
scatter_kernel(const void* __restrict__ ei, const float* __restrict__ ev) {
    int is64 = detect_is64_block((const int*)ei);
    int e4 = blockIdx.x * blockDim.x + threadIdx.x;
    if (e4 < E_NUM / 4) {
        int s[4], d[4];
        load_idx4(ei, 0, e4, is64, s);
        load_idx4(ei, E_NUM, e4, is64, d);
        float4 v = __ldg(&((const float4*)ev)[e4]);
        int p0 = atomicAdd(&g_cursor[d[0]], 1);
        int p1 = atomicAdd(&g_cursor[d[1]], 1);
        int p2 = atomicAdd(&g_cursor[d[2]], 1);
        int p3 = atomicAdd(&g_cursor[d[3]], 1);
        g_edge[p0] = make_int2(s[0], __float_as_int(v.x));
        g_edge[p1] = make_int2(s[1], __float_as_int(v.y));
        g_edge[p2] = make_int2(s[2], __float_as_int(v.z));
        g_edge[p3] = make_int2(s[3], __float_as_int(v.w));
    }
}

// ---------------- agg1: t1[r,0:100] = sum emb[src]*val (1 row/warp) --------
__global__ void __launch_bounds__(256)
agg1_kernel(const float4* __restrict__ h, float4* __restrict__ out, int nRows) {
    const int g = threadIdx.x >> 5;
    const int lane = threadIdx.x & 31;
    const int r = blockIdx.x * 8 + g;
    if (r >= nRows) return;
    const bool act = lane < 25;
    const int beg = g_starts[r];
    const int end = g_starts[r + 1];

    float4 acc = make_float4(0.f, 0.f, 0.f, 0.f);
    int i = beg;
    for (; i + 3 < end; i += 4) {
        int2 e0 = __ldg(&g_edge[i]),     e1 = __ldg(&g_edge[i + 1]);
        int2 e2 = __ldg(&g_edge[i + 2]), e3 = __ldg(&g_edge[i + 3]);
        if (act) {
            float4 x0 = __ldg(&h[(long long)e0.x * 25 + lane]);
            float4 x1 = __ldg(&h[(long long)e1.x * 25 + lane]);
            float4 x2 = __ldg(&h[(long long)e2.x * 25 + lane]);
            float4 x3 = __ldg(&h[(long long)e3.x * 25 + lane]);
            float v0 = __int_as_float(e0.y), v1 = __int_as_float(e1.y);
            float v2 = __int_as_float(e2.y), v3 = __int_as_float(e3.y);
            acc.x = fmaf(x0.x, v0, acc.x); acc.y = fmaf(x0.y, v0, acc.y);
            acc.z = fmaf(x0.z, v0, acc.z); acc.w = fmaf(x0.w, v0, acc.w);
            acc.x = fmaf(x1.x, v1, acc.x); acc.y = fmaf(x1.y, v1, acc.y);
            acc.z = fmaf(x1.z, v1, acc.z); acc.w = fmaf(x1.w, v1, acc.w);
            acc.x = fmaf(x2.x, v2, acc.x); acc.y = fmaf(x2.y, v2, acc.y);
            acc.z = fmaf(x2.z, v2, acc.z); acc.w = fmaf(x2.w, v2, acc.w);
            acc.x = fmaf(x3.x, v3, acc.x); acc.y = fmaf(x3.y, v3, acc.y);
            acc.z = fmaf(x3.z, v3, acc.z); acc.w = fmaf(x3.w, v3, acc.w);
        }
    }
    for (; i < end; i++) {
        int2 e0 = __ldg(&g_edge[i]);
        if (act) {
            float v0 = __int_as_float(e0.y);
            float4 x0 = __ldg(&h[(long long)e0.x * 25 + lane]);
            acc.x = fmaf(x0.x, v0, acc.x); acc.y = fmaf(x0.y, v0, acc.y);
            acc.z = fmaf(x0.z, v0, acc.z); acc.w = fmaf(x0.w, v0, acc.w);
        }
    }
    if (act) out[(long long)r * 25 + lane] = acc;
}

// ---------------- aggH: t2[r,0:200] = sum h1[src]*val (no activation) ------
__global__ void __launch_bounds__(256)
aggH_kernel(const float4* __restrict__ h, float4* __restrict__ out, int nRows) {
    const int g = threadIdx.x >> 6;
    const int t = threadIdx.x & 63;
    const int r = blockIdx.x * 4 + g;
    const bool rowok = r < nRows;
    const bool act = rowok && (t < 50);
    const int beg = rowok ? g_starts[r] : 0;
    const int end = rowok ? g_starts[r + 1] : 0;

    float4 acc = make_float4(0.f, 0.f, 0.f, 0.f);
    int i = beg;
    for (; i + 3 < end; i += 4) {
        int2 e0 = __ldg(&g_edge[i]),     e1 = __ldg(&g_edge[i + 1]);
        int2 e2 = __ldg(&g_edge[i + 2]), e3 = __ldg(&g_edge[i + 3]);
        if (act) {
            float4 x0 = __ldg(&h[(long long)e0.x * 50 + t]);
            float4 x1 = __ldg(&h[(long long)e1.x * 50 + t]);
            float4 x2 = __ldg(&h[(long long)e2.x * 50 + t]);
            float4 x3 = __ldg(&h[(long long)e3.x * 50 + t]);
            float v0 = __int_as_float(e0.y), v1 = __int_as_float(e1.y);
            float v2 = __int_as_float(e2.y), v3 = __int_as_float(e3.y);
            acc.x = fmaf(x0.x, v0, acc.x); acc.y = fmaf(x0.y, v0, acc.y);
            acc.z = fmaf(x0.z, v0, acc.z); acc.w = fmaf(x0.w, v0, acc.w);
            acc.x = fmaf(x1.x, v1, acc.x); acc.y = fmaf(x1.y, v1, acc.y);
            acc.z = fmaf(x1.z, v1, acc.z); acc.w = fmaf(x1.w, v1, acc.w);
            acc.x = fmaf(x2.x, v2, acc.x); acc.y = fmaf(x2.y, v2, acc.y);
            acc.z = fmaf(x2.z, v2, acc.z); acc.w = fmaf(x2.w, v2, acc.w);
            acc.x = fmaf(x3.x, v3, acc.x); acc.y = fmaf(x3.y, v3, acc.y);
            acc.z = fmaf(x3.z, v3, acc.z); acc.w = fmaf(x3.w, v3, acc.w);
        }
    }
    for (; i < end; i++) {
        int2 e0 = __ldg(&g_edge[i]);
        if (act) {
            float v0 = __int_as_float(e0.y);
            float4 x0 = __ldg(&h[(long long)e0.x * 50 + t]);
            acc.x = fmaf(x0.x, v0, acc.x); acc.y = fmaf(x0.y, v0, acc.y);
            acc.z = fmaf(x0.z, v0, acc.z); acc.w = fmaf(x0.w, v0, acc.w);
        }
    }
    if (act) out[(long long)r * 50 + t] = acc;
}

// ---------------- tf32 HMMA GEMM: C = postproc(A @ W) ----------------------
// Block 256 thr = 8 warps (4 over M=64, 2 over N: 13+12 n8-tiles).
// NORM: LeakyReLU + row L2-normalize fused in epilogue (block owns full rows).
#define CK 40
template <int K, int KP, bool LEAKY, bool NORM>
__global__ void __launch_bounds__(256)
gemm_tf32_kernel(const float* __restrict__ A, const float* __restrict__ W,
                 float* __restrict__ C, int nRows) {
    __shared__ unsigned a_s[64][44];
    __shared__ unsigned w_s[CK][200];
    __shared__ float ssum[64][2];
    const int tid = threadIdx.x;
    const int wid = tid >> 5;
    const int lane = tid & 31;
    const int grp = lane >> 2;
    const int tig = lane & 3;
    const int wm = wid & 3;
    const int wn = wid >> 2;
    const int jbase = wn ? 13 : 0;
    const int jcount = wn ? 12 : 13;
    const int r0 = blockIdx.x * 64;

    float acc[13][4];
    #pragma unroll
    for (int j = 0; j < 13; j++)
        #pragma unroll
        for (int c = 0; c < 4; c++) acc[j][c] = 0.f;

    #pragma unroll
    for (int ch = 0; ch < KP / CK; ch++) {
        const int k0 = ch * CK;
        #pragma unroll
        for (int i = 0; i < 3; i++) {
            int idx4 = tid + i * 256;
            if (idx4 < 640) {
                int row = idx4 / 10;
                int q = idx4 % 10;
                int gr = r0 + row;
                float4 v = make_float4(0.f, 0.f, 0.f, 0.f);
                if (gr < nRows && k0 + q * 4 < K)
                    v = *(const float4*)&A[(long long)gr * K + k0 + q * 4];
                a_s[row][q * 4 + 0] = tf32_of(v.x);
                a_s[row][q * 4 + 1] = tf32_of(v.y);
                a_s[row][q * 4 + 2] = tf32_of(v.z);
                a_s[row][q * 4 + 3] = tf32_of(v.w);
            }
        }
        #pragma unroll
        for (int i = 0; i < 8; i++) {
            int idx4 = tid + i * 256;
            if (idx4 < 2000) {
                int kk = idx4 / 50;
                int c4 = idx4 % 50;
                float4 v = make_float4(0.f, 0.f, 0.f, 0.f);
                if (k0 + kk < K)
                    v = *(const float4*)&W[(k0 + kk) * 200 + c4 * 4];
                w_s[kk][c4 * 4 + 0] = tf32_of(v.x);
                w_s[kk][c4 * 4 + 1] = tf32_of(v.y);
                w_s[kk][c4 * 4 + 2] = tf32_of(v.z);
                w_s[kk][c4 * 4 + 3] = tf32_of(v.w);
            }
        }
        __syncthreads();

        #pragma unroll
        for (int ks = 0; ks < CK / 8; ks++) {
            const int kk = ks * 8;
            unsigned a0 = a_s[wm * 16 + grp][kk + tig];
            unsigned a1 = a_s[wm * 16 + grp + 8][kk + tig];
            unsigned a2 = a_s[wm * 16 + grp][kk + tig + 4];
            unsigned a3 = a_s[wm * 16 + grp + 8][kk + tig + 4];
            #pragma unroll
            for (int j = 0; j < 13; j++) {
                if (j < jcount) {
                    int n0 = (jbase + j) * 8;
                    unsigned b0 = w_s[kk + tig][n0 + grp];
                    unsigned b1 = w_s[kk + tig + 4][n0 + grp];
                    mma_tf32(acc[j][0], acc[j][1], acc[j][2], acc[j][3],
                             a0, a1, a2, a3, b0, b1,
                             acc[j][0], acc[j][1], acc[j][2], acc[j][3]);
                }
            }
        }
        __syncthreads();
    }

    // epilogue
    if (LEAKY || NORM) {
        #pragma unroll
        for (int j = 0; j < 13; j++) {
            if (j < jcount) {
                #pragma unroll
                for (int c = 0; c < 4; c++)
                    acc[j][c] = acc[j][c] > 0.f ? acc[j][c] : ALPHA * acc[j][c];
            }
        }
    }
    float inv_lo = 1.f, inv_hi = 1.f;
    if (NORM) {
        float slo = 0.f, shi = 0.f;
        #pragma unroll
        for (int j = 0; j < 13; j++) {
            if (j < jcount) {
                slo = fmaf(acc[j][0], acc[j][0], slo);
                slo = fmaf(acc[j][1], acc[j][1], slo);
                shi = fmaf(acc[j][2], acc[j][2], shi);
                shi = fmaf(acc[j][3], acc[j][3], shi);
            }
        }
        // reduce over tig (lanes grp*4 .. grp*4+3)
        #pragma unroll
        for (int o = 1; o <= 2; o <<= 1) {
            slo += __shfl_xor_sync(0xffffffffu, slo, o);
            shi += __shfl_xor_sync(0xffffffffu, shi, o);
        }
        if (tig == 0) {
            ssum[wm * 16 + grp][wn] = slo;
            ssum[wm * 16 + grp + 8][wn] = shi;
        }
        __syncthreads();
        float tlo = ssum[wm * 16 + grp][0] + ssum[wm * 16 + grp][1];
        float thi = ssum[wm * 16 + grp + 8][0] + ssum[wm * 16 + grp + 8][1];
        inv_lo = 1.0f / fmaxf(sqrtf(tlo), EPSN);
        inv_hi = 1.0f / fmaxf(sqrtf(thi), EPSN);
    }

    const int row_lo = r0 + wm * 16 + grp;
    const int row_hi = row_lo + 8;
    #pragma unroll
    for (int j = 0; j < 13; j++) {
        if (j < jcount) {
            int col = (jbase + j) * 8 + tig * 2;
            float o0 = acc[j][0] * inv_lo, o1 = acc[j][1] * inv_lo;
            float o2 = acc[j][2] * inv_hi, o3 = acc[j][3] * inv_hi;
            if (row_lo < nRows) *(float2*)&C[(long long)row_lo * 200 + col] = make_float2(o0, o1);
            if (row_hi < nRows) *(float2*)&C[(long long)row_hi * 200 + col] = make_float2(o2, o3);
        }
    }
}

// ---------------- launch ----------------
extern "C" void kernel_launch(void* const* d_in, const int* in_sizes, int n_in,
                              void* d_out, int out_size) {
    const float* emb = (const float*)d_in[0];        // [N_TOT, 100]
    const float* W1  = (const float*)d_in[1];        // [100, 200]
    const float* W2  = (const float*)d_in[2];        // [200, 200]
    const void*  ei  = d_in[3];                      // [2, E]
    const float* ev  = (const float*)d_in[4];        // [E]
    float* out = (float*)d_out;                      // [N_TOT, 200]

    float* buf0; cudaGetSymbolAddress((void**)&buf0, g_buf0);
    float* h1;   cudaGetSymbolAddress((void**)&h1, g_h1);

    // CSR build (3 launches, 4 edges/thread)
    hist_kernel<<<(E_NUM / 4 + 255) / 256, 256>>>(ei);
    scan_kernel<<<SCAN_NB, SCAN_BLK>>>();
    scatter_kernel<<<(E_NUM / 4 + 255) / 256, 256>>>(ei, ev);

    int ggrid = (N_TOT + 63) / 64;

    // Layer 1: agg(raw emb) -> gemm1(+leaky)            [linearity]
    agg1_kernel<<<(N_TOT + 7) / 8, 256>>>((const float4*)emb, (float4*)buf0, N_TOT);
    gemm_tf32_kernel<D_IN, 120, true, false><<<ggrid, 256>>>(buf0, W1, h1, N_TOT);

    // Layer 2: agg(h1) -> gemm2(+leaky+norm) -> d_out   [linearity]
    aggH_kernel<<<(N_TOT + 3) / 4, 256>>>((const float4*)h1, (float4*)buf0, N_TOT);
    gemm_tf32_kernel<D_OUT, 200, true, true><<<ggrid, 256>>>(buf0, W2, out, N_TOT);
}

// round 6
// speedup vs baseline: 2.3670x; 1.1243x over previous
#include <cuda_runtime.h>
#include <cuda_fp16.h>
#include <cstdint>

#define N_ENT 50000
#define N_REL 500
#define N_TOT (N_ENT + N_REL)   // 50500
#define E_NUM 800000
#define D_IN  100
#define D_OUT 200
#define ALPHA 0.2f
#define EPSN  1e-12f

#define SCAN_BLK 1024
#define SCAN_NB  ((N_TOT + SCAN_BLK - 1) / SCAN_BLK)   // 50

// ---------------- scratch (device globals; zero-initialized at load) -------
__device__ __half g_bufh[N_TOT * D_OUT];  // agg1 out [N,100] / aggH out [N,200] (fp16)
__device__ __half g_h1h[N_TOT * D_OUT];   // layer-1 output [N,200] (fp16)
__device__ int    g_counts[N_TOT];        // zeroed at load; re-zeroed by scan
__device__ int    g_starts[N_TOT + 1];
__device__ int    g_cursor[N_TOT];
__device__ int    g_bsum[SCAN_NB];
__device__ int    g_flag[SCAN_NB];        // lookback flags; reset by hist blk0
__device__ int2   g_edge[E_NUM];          // dst-sorted (src, val_bits)

// ---------------- helpers ----------------
__device__ __forceinline__ int detect_is64_block(const int* ei_words) {
    __shared__ int s_is64;
    if (threadIdx.x == 0) {
        int f = 1;
        #pragma unroll 8
        for (int j = 1; j < 256; j += 2)
            if (ei_words[j] != 0) f = 0;
        s_is64 = f;
    }
    __syncthreads();
    return s_is64;
}
__device__ __forceinline__ unsigned tf32_of(float x) {
    unsigned r;
    asm("cvt.rna.tf32.f32 %0, %1;" : "=r"(r) : "f"(x));
    return r;
}
__device__ __forceinline__ void mma_tf32(float& d0, float& d1, float& d2, float& d3,
                                         unsigned a0, unsigned a1, unsigned a2, unsigned a3,
                                         unsigned b0, unsigned b1,
                                         float c0, float c1, float c2, float c3) {
    asm("mma.sync.aligned.m16n8k8.row.col.f32.tf32.tf32.f32 "
        "{%0,%1,%2,%3},{%4,%5,%6,%7},{%8,%9},{%10,%11,%12,%13};"
        : "=f"(d0), "=f"(d1), "=f"(d2), "=f"(d3)
        : "r"(a0), "r"(a1), "r"(a2), "r"(a3), "r"(b0), "r"(b1),
          "f"(c0), "f"(c1), "f"(c2), "f"(c3));
}
__device__ __forceinline__ void load_idx4(const void* ei, long long base, int e4,
                                          int is64, int d[4]) {
    if (is64) {
        const longlong2* p = (const longlong2*)ei;
        long long off = (base + 4LL * e4) >> 1;
        longlong2 a = __ldg(&p[off]);
        longlong2 b = __ldg(&p[off + 1]);
        d[0] = (int)a.x; d[1] = (int)a.y; d[2] = (int)b.x; d[3] = (int)b.y;
    } else {
        const int4* p = (const int4*)ei;
        int4 a = __ldg(&p[(base + 4LL * e4) >> 2]);
        d[0] = a.x; d[1] = a.y; d[2] = a.z; d[3] = a.w;
    }
}

// ---------------- hist: 4 edges/thread; block 0 resets lookback flags ------
__global__ void __launch_bounds__(256)
hist_kernel(const void* __restrict__ ei) {
    int is64 = detect_is64_block((const int*)ei);
    if (blockIdx.x == 0 && threadIdx.x < SCAN_NB) g_flag[threadIdx.x] = 0;
    int e4 = blockIdx.x * blockDim.x + threadIdx.x;
    if (e4 < E_NUM / 4) {
        int d[4];
        load_idx4(ei, E_NUM, e4, is64, d);
        atomicAdd(&g_counts[d[0]], 1);
        atomicAdd(&g_counts[d[1]], 1);
        atomicAdd(&g_counts[d[2]], 1);
        atomicAdd(&g_counts[d[3]], 1);
    }
}

// ---------------- single-pass scan with decoupled lookback -----------------
__global__ void __launch_bounds__(SCAN_BLK)
scan_kernel() {
    __shared__ int woff[32];
    __shared__ int s_off[2];
    const int tid = threadIdx.x;
    const int lane = tid & 31;
    const int wid = tid >> 5;
    const int b = blockIdx.x;
    const int i = b * SCAN_BLK + tid;

    int v = (i < N_TOT) ? g_counts[i] : 0;
    if (i < N_TOT) g_counts[i] = 0;        // re-zero for next replay

    int incl = v;
    #pragma unroll
    for (int o = 1; o < 32; o <<= 1) {
        int t = __shfl_up_sync(0xffffffffu, incl, o);
        if (lane >= o) incl += t;
    }
    if (lane == 31) woff[wid] = incl;
    __syncthreads();
    if (wid == 0) {
        int w = woff[lane];
        int wincl = w;
        #pragma unroll
        for (int o = 1; o < 32; o <<= 1) {
            int t = __shfl_up_sync(0xffffffffu, wincl, o);
            if (lane >= o) wincl += t;
        }
        woff[lane] = wincl - w;
        if (lane == 31) {
            g_bsum[b] = wincl;
            __threadfence();
            atomicExch(&g_flag[b], 1);
        }
    }
    __syncthreads();

    if (tid < 64) {
        int offv = 0;
        if (tid < b) {
            while (atomicAdd(&g_flag[tid], 0) == 0) { }
            __threadfence();
            offv = g_bsum[tid];
        }
        #pragma unroll
        for (int o = 16; o; o >>= 1) offv += __shfl_down_sync(0xffffffffu, offv, o);
        if ((tid & 31) == 0) s_off[tid >> 5] = offv;
    }
    __syncthreads();
    int off = s_off[0] + s_off[1];

    if (i < N_TOT) {
        int s = off + woff[wid] + (incl - v);
        g_starts[i] = s;
        g_cursor[i] = s;
    }
    if (b == SCAN_NB - 1 && tid == 0)
        g_starts[N_TOT] = off + g_bsum[b];
}

// ---------------- scatter: 4 edges/thread, packed STG.64 -------------------
__global__ void __launch_bounds__(256)
scatter_kernel(const void* __restrict__ ei, const float* __restrict__ ev) {
    int is64 = detect_is64_block((const int*)ei);
    int e4 = blockIdx.x * blockDim.x + threadIdx.x;
    if (e4 < E_NUM / 4) {
        int s[4], d[4];
        load_idx4(ei, 0, e4, is64, s);
        load_idx4(ei, E_NUM, e4, is64, d);
        float4 v = __ldg(&((const float4*)ev)[e4]);
        int p0 = atomicAdd(&g_cursor[d[0]], 1);
        int p1 = atomicAdd(&g_cursor[d[1]], 1);
        int p2 = atomicAdd(&g_cursor[d[2]], 1);
        int p3 = atomicAdd(&g_cursor[d[3]], 1);
        g_edge[p0] = make_int2(s[0], __float_as_int(v.x));
        g_edge[p1] = make_int2(s[1], __float_as_int(v.y));
        g_edge[p2] = make_int2(s[2], __float_as_int(v.z));
        g_edge[p3] = make_int2(s[3], __float_as_int(v.w));
    }
}

// ---------------- agg1: bufh[r,0:100] = fp16( sum emb[src]*val ) -----------
// 1 row/warp; lanes 0..24 carry one float4; output packed as 4 halves (uint2).
__global__ void __launch_bounds__(256)
agg1_kernel(const float4* __restrict__ h, __half* __restrict__ out, int nRows) {
    const int g = threadIdx.x >> 5;
    const int lane = threadIdx.x & 31;
    const int r = blockIdx.x * 8 + g;
    if (r >= nRows) return;
    const bool act = lane < 25;
    const int beg = g_starts[r];
    const int end = g_starts[r + 1];

    float4 acc = make_float4(0.f, 0.f, 0.f, 0.f);
    int i = beg;
    for (; i + 3 < end; i += 4) {
        int2 e0 = __ldg(&g_edge[i]),     e1 = __ldg(&g_edge[i + 1]);
        int2 e2 = __ldg(&g_edge[i + 2]), e3 = __ldg(&g_edge[i + 3]);
        if (act) {
            float4 x0 = __ldg(&h[(long long)e0.x * 25 + lane]);
            float4 x1 = __ldg(&h[(long long)e1.x * 25 + lane]);
            float4 x2 = __ldg(&h[(long long)e2.x * 25 + lane]);
            float4 x3 = __ldg(&h[(long long)e3.x * 25 + lane]);
            float v0 = __int_as_float(e0.y), v1 = __int_as_float(e1.y);
            float v2 = __int_as_float(e2.y), v3 = __int_as_float(e3.y);
            acc.x = fmaf(x0.x, v0, acc.x); acc.y = fmaf(x0.y, v0, acc.y);
            acc.z = fmaf(x0.z, v0, acc.z); acc.w = fmaf(x0.w, v0, acc.w);
            acc.x = fmaf(x1.x, v1, acc.x); acc.y = fmaf(x1.y, v1, acc.y);
            acc.z = fmaf(x1.z, v1, acc.z); acc.w = fmaf(x1.w, v1, acc.w);
            acc.x = fmaf(x2.x, v2, acc.x); acc.y = fmaf(x2.y, v2, acc.y);
            acc.z = fmaf(x2.z, v2, acc.z); acc.w = fmaf(x2.w, v2, acc.w);
            acc.x = fmaf(x3.x, v3, acc.x); acc.y = fmaf(x3.y, v3, acc.y);
            acc.z = fmaf(x3.z, v3, acc.z); acc.w = fmaf(x3.w, v3, acc.w);
        }
    }
    for (; i < end; i++) {
        int2 e0 = __ldg(&g_edge[i]);
        if (act) {
            float v0 = __int_as_float(e0.y);
            float4 x0 = __ldg(&h[(long long)e0.x * 25 + lane]);
            acc.x = fmaf(x0.x, v0, acc.x); acc.y = fmaf(x0.y, v0, acc.y);
            acc.z = fmaf(x0.z, v0, acc.z); acc.w = fmaf(x0.w, v0, acc.w);
        }
    }
    if (act) {
        __half2 h0 = __float22half2_rn(make_float2(acc.x, acc.y));
        __half2 h1 = __float22half2_rn(make_float2(acc.z, acc.w));
        uint2 u = make_uint2(*(unsigned*)&h0, *(unsigned*)&h1);
        *(uint2*)&out[(long long)r * 100 + lane * 4] = u;
    }
}

// ---------------- aggH: bufh[r,0:200] = fp16( sum h1h[src]*val ) -----------
// 1 row/warp; lanes 0..24 load uint4 = 8 halves; fp32 accumulate.
__global__ void __launch_bounds__(256)
aggH_kernel(const uint4* __restrict__ h, uint4* __restrict__ out, int nRows) {
    const int g = threadIdx.x >> 5;
    const int lane = threadIdx.x & 31;
    const int r = blockIdx.x * 8 + g;
    if (r >= nRows) return;
    const bool act = lane < 25;
    const int beg = g_starts[r];
    const int end = g_starts[r + 1];

    float acc[8];
    #pragma unroll
    for (int c = 0; c < 8; c++) acc[c] = 0.f;

    int i = beg;
    for (; i + 3 < end; i += 4) {
        int2 e0 = __ldg(&g_edge[i]),     e1 = __ldg(&g_edge[i + 1]);
        int2 e2 = __ldg(&g_edge[i + 2]), e3 = __ldg(&g_edge[i + 3]);
        if (act) {
            uint4 u0 = __ldg(&h[(long long)e0.x * 25 + lane]);
            uint4 u1 = __ldg(&h[(long long)e1.x * 25 + lane]);
            uint4 u2 = __ldg(&h[(long long)e2.x * 25 + lane]);
            uint4 u3 = __ldg(&h[(long long)e3.x * 25 + lane]);
            float v0 = __int_as_float(e0.y), v1 = __int_as_float(e1.y);
            float v2 = __int_as_float(e2.y), v3 = __int_as_float(e3.y);
            const unsigned* w0 = &u0.x;
            const unsigned* w1 = &u1.x;
            const unsigned* w2 = &u2.x;
            const unsigned* w3 = &u3.x;
            #pragma unroll
            for (int q = 0; q < 4; q++) {
                float2 f0 = __half22float2(*(const __half2*)&w0[q]);
                float2 f1 = __half22float2(*(const __half2*)&w1[q]);
                float2 f2 = __half22float2(*(const __half2*)&w2[q]);
                float2 f3 = __half22float2(*(const __half2*)&w3[q]);
                acc[q * 2]     = fmaf(f0.x, v0, acc[q * 2]);
                acc[q * 2 + 1] = fmaf(f0.y, v0, acc[q * 2 + 1]);
                acc[q * 2]     = fmaf(f1.x, v1, acc[q * 2]);
                acc[q * 2 + 1] = fmaf(f1.y, v1, acc[q * 2 + 1]);
                acc[q * 2]     = fmaf(f2.x, v2, acc[q * 2]);
                acc[q * 2 + 1] = fmaf(f2.y, v2, acc[q * 2 + 1]);
                acc[q * 2]     = fmaf(f3.x, v3, acc[q * 2]);
                acc[q * 2 + 1] = fmaf(f3.y, v3, acc[q * 2 + 1]);
            }
        }
    }
    for (; i < end; i++) {
        int2 e0 = __ldg(&g_edge[i]);
        if (act) {
            float v0 = __int_as_float(e0.y);
            uint4 u0 = __ldg(&h[(long long)e0.x * 25 + lane]);
            const unsigned* w0 = &u0.x;
            #pragma unroll
            for (int q = 0; q < 4; q++) {
                float2 f0 = __half22float2(*(const __half2*)&w0[q]);
                acc[q * 2]     = fmaf(f0.x, v0, acc[q * 2]);
                acc[q * 2 + 1] = fmaf(f0.y, v0, acc[q * 2 + 1]);
            }
        }
    }
    if (act) {
        uint4 u;
        __half2 p0 = __float22half2_rn(make_float2(acc[0], acc[1]));
        __half2 p1 = __float22half2_rn(make_float2(acc[2], acc[3]));
        __half2 p2 = __float22half2_rn(make_float2(acc[4], acc[5]));
        __half2 p3 = __float22half2_rn(make_float2(acc[6], acc[7]));
        u.x = *(unsigned*)&p0; u.y = *(unsigned*)&p1;
        u.z = *(unsigned*)&p2; u.w = *(unsigned*)&p3;
        out[(long long)r * 25 + lane] = u;
    }
}

// ---------------- tf32 HMMA GEMM: C = postproc(A_half @ W_f32) -------------
// Block 256 thr = 8 warps (4 over M=64, 2 over N: 13+12 n8-tiles).
// HALF_OUT: write C as fp16; NORM: leaky + row L2-normalize, C fp32 (d_out).
#define CK 40
template <int K, int KP, bool LEAKY, bool NORM, bool HALF_OUT>
__global__ void __launch_bounds__(256)
gemm_tf32_kernel(const __half* __restrict__ A, const float* __restrict__ W,
                 void* __restrict__ Cv, int nRows) {
    __shared__ unsigned a_s[64][44];
    __shared__ unsigned w_s[CK][200];
    __shared__ float ssum[64][2];
    const int tid = threadIdx.x;
    const int wid = tid >> 5;
    const int lane = tid & 31;
    const int grp = lane >> 2;
    const int tig = lane & 3;
    const int wm = wid & 3;
    const int wn = wid >> 2;
    const int jbase = wn ? 13 : 0;
    const int jcount = wn ? 12 : 13;
    const int r0 = blockIdx.x * 64;

    float acc[13][4];
    #pragma unroll
    for (int j = 0; j < 13; j++)
        #pragma unroll
        for (int c = 0; c < 4; c++) acc[j][c] = 0.f;

    #pragma unroll
    for (int ch = 0; ch < KP / CK; ch++) {
        const int k0 = ch * CK;
        // stage A chunk: 64 rows x 40 k, fp16 source (uint2 = 4 halves)
        #pragma unroll
        for (int i = 0; i < 3; i++) {
            int idx4 = tid + i * 256;
            if (idx4 < 640) {
                int row = idx4 / 10;
                int q = idx4 % 10;
                int gr = r0 + row;
                float f[4] = {0.f, 0.f, 0.f, 0.f};
                if (gr < nRows && k0 + q * 4 < K) {
                    uint2 u = *(const uint2*)&A[(long long)gr * K + k0 + q * 4];
                    float2 a = __half22float2(*(const __half2*)&u.x);
                    float2 b = __half22float2(*(const __half2*)&u.y);
                    f[0] = a.x; f[1] = a.y; f[2] = b.x; f[3] = b.y;
                }
                a_s[row][q * 4 + 0] = tf32_of(f[0]);
                a_s[row][q * 4 + 1] = tf32_of(f[1]);
                a_s[row][q * 4 + 2] = tf32_of(f[2]);
                a_s[row][q * 4 + 3] = tf32_of(f[3]);
            }
        }
        #pragma unroll
        for (int i = 0; i < 8; i++) {
            int idx4 = tid + i * 256;
            if (idx4 < 2000) {
                int kk = idx4 / 50;
                int c4 = idx4 % 50;
                float4 v = make_float4(0.f, 0.f, 0.f, 0.f);
                if (k0 + kk < K)
                    v = *(const float4*)&W[(k0 + kk) * 200 + c4 * 4];
                w_s[kk][c4 * 4 + 0] = tf32_of(v.x);
                w_s[kk][c4 * 4 + 1] = tf32_of(v.y);
                w_s[kk][c4 * 4 + 2] = tf32_of(v.z);
                w_s[kk][c4 * 4 + 3] = tf32_of(v.w);
            }
        }
        __syncthreads();

        #pragma unroll
        for (int ks = 0; ks < CK / 8; ks++) {
            const int kk = ks * 8;
            unsigned a0 = a_s[wm * 16 + grp][kk + tig];
            unsigned a1 = a_s[wm * 16 + grp + 8][kk + tig];
            unsigned a2 = a_s[wm * 16 + grp][kk + tig + 4];
            unsigned a3 = a_s[wm * 16 + grp + 8][kk + tig + 4];
            #pragma unroll
            for (int j = 0; j < 13; j++) {
                if (j < jcount) {
                    int n0 = (jbase + j) * 8;
                    unsigned b0 = w_s[kk + tig][n0 + grp];
                    unsigned b1 = w_s[kk + tig + 4][n0 + grp];
                    mma_tf32(acc[j][0], acc[j][1], acc[j][2], acc[j][3],
                             a0, a1, a2, a3, b0, b1,
                             acc[j][0], acc[j][1], acc[j][2], acc[j][3]);
                }
            }
        }
        __syncthreads();
    }

    if (LEAKY || NORM) {
        #pragma unroll
        for (int j = 0; j < 13; j++) {
            if (j < jcount) {
                #pragma unroll
                for (int c = 0; c < 4; c++)
                    acc[j][c] = acc[j][c] > 0.f ? acc[j][c] : ALPHA * acc[j][c];
            }
        }
    }
    float inv_lo = 1.f, inv_hi = 1.f;
    if (NORM) {
        float slo = 0.f, shi = 0.f;
        #pragma unroll
        for (int j = 0; j < 13; j++) {
            if (j < jcount) {
                slo = fmaf(acc[j][0], acc[j][0], slo);
                slo = fmaf(acc[j][1], acc[j][1], slo);
                shi = fmaf(acc[j][2], acc[j][2], shi);
                shi = fmaf(acc[j][3], acc[j][3], shi);
            }
        }
        #pragma unroll
        for (int o = 1; o <= 2; o <<= 1) {
            slo += __shfl_xor_sync(0xffffffffu, slo, o);
            shi += __shfl_xor_sync(0xffffffffu, shi, o);
        }
        if (tig == 0) {
            ssum[wm * 16 + grp][wn] = slo;
            ssum[wm * 16 + grp + 8][wn] = shi;
        }
        __syncthreads();
        float tlo = ssum[wm * 16 + grp][0] + ssum[wm * 16 + grp][1];
        float thi = ssum[wm * 16 + grp + 8][0] + ssum[wm * 16 + grp + 8][1];
        inv_lo = 1.0f / fmaxf(sqrtf(tlo), EPSN);
        inv_hi = 1.0f / fmaxf(sqrtf(thi), EPSN);
    }

    const int row_lo = r0 + wm * 16 + grp;
    const int row_hi = row_lo + 8;
    #pragma unroll
    for (int j = 0; j < 13; j++) {
        if (j < jcount) {
            int col = (jbase + j) * 8 + tig * 2;
            float o0 = acc[j][0] * inv_lo, o1 = acc[j][1] * inv_lo;
            float o2 = acc[j][2] * inv_hi, o3 = acc[j][3] * inv_hi;
            if (HALF_OUT) {
                __half* C = (__half*)Cv;
                __half2 plo = __float22half2_rn(make_float2(o0, o1));
                __half2 phi = __float22half2_rn(make_float2(o2, o3));
                if (row_lo < nRows) *(__half2*)&C[(long long)row_lo * 200 + col] = plo;
                if (row_hi < nRows) *(__half2*)&C[(long long)row_hi * 200 + col] = phi;
            } else {
                float* C = (float*)Cv;
                if (row_lo < nRows) *(float2*)&C[(long long)row_lo * 200 + col] = make_float2(o0, o1);
                if (row_hi < nRows) *(float2*)&C[(long long)row_hi * 200 + col] = make_float2(o2, o3);
            }
        }
    }
}

// ---------------- launch ----------------
extern "C" void kernel_launch(void* const* d_in, const int* in_sizes, int n_in,
                              void* d_out, int out_size) {
    const float* emb = (const float*)d_in[0];        // [N_TOT, 100]
    const float* W1  = (const float*)d_in[1];        // [100, 200]
    const float* W2  = (const float*)d_in[2];        // [200, 200]
    const void*  ei  = d_in[3];                      // [2, E]
    const float* ev  = (const float*)d_in[4];        // [E]
    float* out = (float*)d_out;                      // [N_TOT, 200]

    __half* bufh; cudaGetSymbolAddress((void**)&bufh, g_bufh);
    __half* h1h;  cudaGetSymbolAddress((void**)&h1h, g_h1h);

    // CSR build
    hist_kernel<<<(E_NUM / 4 + 255) / 256, 256>>>(ei);
    scan_kernel<<<SCAN_NB, SCAN_BLK>>>();
    scatter_kernel<<<(E_NUM / 4 + 255) / 256, 256>>>(ei, ev);

    int ggrid = (N_TOT + 63) / 64;

    // Layer 1: agg(raw emb fp32) -> fp16; gemm1(+leaky) -> h1 fp16
    agg1_kernel<<<(N_TOT + 7) / 8, 256>>>((const float4*)emb, bufh, N_TOT);
    gemm_tf32_kernel<D_IN, 120, true, false, true><<<ggrid, 256>>>(bufh, W1, h1h, N_TOT);

    // Layer 2: agg(h1 fp16) -> fp16; gemm2(+leaky+norm) -> d_out fp32
    aggH_kernel<<<(N_TOT + 7) / 8, 256>>>((const uint4*)h1h, (uint4*)bufh, N_TOT);
    gemm_tf32_kernel<D_OUT, 200, true, true, false><<<ggrid, 256>>>(bufh, W2, out, N_TOT);
}

// round 7
// speedup vs baseline: 2.3784x; 1.0048x over previous
#include <cuda_runtime.h>
#include <cuda_fp16.h>
#include <cstdint>

#define N_ENT 50000
#define N_REL 500
#define N_TOT (N_ENT + N_REL)   // 50500
#define E_NUM 800000
#define D_IN  100
#define D_OUT 200
#define ALPHA 0.2f
#define EPSN  1e-12f

#define SCAN_BLK 1024
#define SCAN_NB  ((N_TOT + SCAN_BLK - 1) / SCAN_BLK)   // 50

// ---------------- scratch (device globals; zero-initialized at load) -------
__device__ __half g_embh[N_TOT * D_IN];   // fp16 copy of embeddings
__device__ __half g_bufh[N_TOT * D_OUT];  // agg1 out [N,100] / aggH out [N,200]
__device__ __half g_h1h[N_TOT * D_OUT];   // layer-1 output [N,200]
__device__ int    g_counts[N_TOT];        // zeroed at load; re-zeroed by scan
__device__ int    g_starts[N_TOT + 1];
__device__ int    g_cursor[N_TOT];
__device__ int    g_bsum[SCAN_NB];
__device__ int    g_flag[SCAN_NB];        // lookback flags; reset by hist blk0
__device__ int2   g_edge[E_NUM];          // dst-sorted (src, val_bits)

// ---------------- helpers ----------------
__device__ __forceinline__ int detect_is64_block(const int* ei_words) {
    __shared__ int s_is64;
    if (threadIdx.x == 0) {
        int f = 1;
        #pragma unroll 8
        for (int j = 1; j < 256; j += 2)
            if (ei_words[j] != 0) f = 0;
        s_is64 = f;
    }
    __syncthreads();
    return s_is64;
}
__device__ __forceinline__ unsigned tf32_of(float x) {
    unsigned r;
    asm("cvt.rna.tf32.f32 %0, %1;" : "=r"(r) : "f"(x));
    return r;
}
__device__ __forceinline__ void mma_tf32(float& d0, float& d1, float& d2, float& d3,
                                         unsigned a0, unsigned a1, unsigned a2, unsigned a3,
                                         unsigned b0, unsigned b1,
                                         float c0, float c1, float c2, float c3) {
    asm("mma.sync.aligned.m16n8k8.row.col.f32.tf32.tf32.f32 "
        "{%0,%1,%2,%3},{%4,%5,%6,%7},{%8,%9},{%10,%11,%12,%13};"
        : "=f"(d0), "=f"(d1), "=f"(d2), "=f"(d3)
        : "r"(a0), "r"(a1), "r"(a2), "r"(a3), "r"(b0), "r"(b1),
          "f"(c0), "f"(c1), "f"(c2), "f"(c3));
}
__device__ __forceinline__ void load_idx4(const void* ei, long long base, int e4,
                                          int is64, int d[4]) {
    if (is64) {
        const longlong2* p = (const longlong2*)ei;
        long long off = (base + 4LL * e4) >> 1;
        longlong2 a = __ldg(&p[off]);
        longlong2 b = __ldg(&p[off + 1]);
        d[0] = (int)a.x; d[1] = (int)a.y; d[2] = (int)b.x; d[3] = (int)b.y;
    } else {
        const int4* p = (const int4*)ei;
        int4 a = __ldg(&p[(base + 4LL * e4) >> 2]);
        d[0] = a.x; d[1] = a.y; d[2] = a.z; d[3] = a.w;
    }
}

// ---------------- hist + emb->fp16 convert (fused) -------------------------
__global__ void __launch_bounds__(256)
hist_kernel(const void* __restrict__ ei, const float2* __restrict__ emb) {
    int is64 = detect_is64_block((const int*)ei);
    if (blockIdx.x == 0 && threadIdx.x < SCAN_NB) g_flag[threadIdx.x] = 0;
    int gtid = blockIdx.x * blockDim.x + threadIdx.x;
    // histogram (4 edges/thread)
    if (gtid < E_NUM / 4) {
        int d[4];
        load_idx4(ei, E_NUM, gtid, is64, d);
        atomicAdd(&g_counts[d[0]], 1);
        atomicAdd(&g_counts[d[1]], 1);
        atomicAdd(&g_counts[d[2]], 1);
        atomicAdd(&g_counts[d[3]], 1);
    }
    // streaming fp32 -> fp16 conversion of embeddings
    __half2* dst = (__half2*)g_embh;
    const int total2 = N_TOT * D_IN / 2;           // 2,525,000
    const int stride = gridDim.x * blockDim.x;
    for (int i = gtid; i < total2; i += stride)
        dst[i] = __float22half2_rn(__ldg(&emb[i]));
}

// ---------------- single-pass scan with decoupled lookback -----------------
__global__ void __launch_bounds__(SCAN_BLK)
scan_kernel() {
    __shared__ int woff[32];
    __shared__ int s_off[2];
    const int tid = threadIdx.x;
    const int lane = tid & 31;
    const int wid = tid >> 5;
    const int b = blockIdx.x;
    const int i = b * SCAN_BLK + tid;

    int v = (i < N_TOT) ? g_counts[i] : 0;
    if (i < N_TOT) g_counts[i] = 0;        // re-zero for next replay

    int incl = v;
    #pragma unroll
    for (int o = 1; o < 32; o <<= 1) {
        int t = __shfl_up_sync(0xffffffffu, incl, o);
        if (lane >= o) incl += t;
    }
    if (lane == 31) woff[wid] = incl;
    __syncthreads();
    if (wid == 0) {
        int w = woff[lane];
        int wincl = w;
        #pragma unroll
        for (int o = 1; o < 32; o <<= 1) {
            int t = __shfl_up_sync(0xffffffffu, wincl, o);
            if (lane >= o) wincl += t;
        }
        woff[lane] = wincl - w;
        if (lane == 31) {
            g_bsum[b] = wincl;
            __threadfence();
            atomicExch(&g_flag[b], 1);
        }
    }
    __syncthreads();

    if (tid < 64) {
        int offv = 0;
        if (tid < b) {
            while (atomicAdd(&g_flag[tid], 0) == 0) { }
            __threadfence();
            offv = g_bsum[tid];
        }
        #pragma unroll
        for (int o = 16; o; o >>= 1) offv += __shfl_down_sync(0xffffffffu, offv, o);
        if ((tid & 31) == 0) s_off[tid >> 5] = offv;
    }
    __syncthreads();
    int off = s_off[0] + s_off[1];

    if (i < N_TOT) {
        int s = off + woff[wid] + (incl - v);
        g_starts[i] = s;
        g_cursor[i] = s;
    }
    if (b == SCAN_NB - 1 && tid == 0)
        g_starts[N_TOT] = off + g_bsum[b];
}

// ---------------- scatter: 4 edges/thread, packed STG.64 -------------------
__global__ void __launch_bounds__(256)
scatter_kernel(const void* __restrict__ ei, const float* __restrict__ ev) {
    int is64 = detect_is64_block((const int*)ei);
    int e4 = blockIdx.x * blockDim.x + threadIdx.x;
    if (e4 < E_NUM / 4) {
        int s[4], d[4];
        load_idx4(ei, 0, e4, is64, s);
        load_idx4(ei, E_NUM, e4, is64, d);
        float4 v = __ldg(&((const float4*)ev)[e4]);
        int p0 = atomicAdd(&g_cursor[d[0]], 1);
        int p1 = atomicAdd(&g_cursor[d[1]], 1);
        int p2 = atomicAdd(&g_cursor[d[2]], 1);
        int p3 = atomicAdd(&g_cursor[d[3]], 1);
        g_edge[p0] = make_int2(s[0], __float_as_int(v.x));
        g_edge[p1] = make_int2(s[1], __float_as_int(v.y));
        g_edge[p2] = make_int2(s[2], __float_as_int(v.z));
        g_edge[p3] = make_int2(s[3], __float_as_int(v.w));
    }
}

// ---------------- agg1: bufh[r,0:100] = fp16( sum embh[src]*val ) ----------
// 1 row/warp; lanes 0..24 gather uint2 = 4 halves; fp32 accumulate.
__global__ void __launch_bounds__(256)
agg1_kernel(const uint2* __restrict__ h, __half* __restrict__ out, int nRows) {
    const int g = threadIdx.x >> 5;
    const int lane = threadIdx.x & 31;
    const int r = blockIdx.x * 8 + g;
    if (r >= nRows) return;
    const bool act = lane < 25;
    const int beg = g_starts[r];
    const int end = g_starts[r + 1];

    float acc[4] = {0.f, 0.f, 0.f, 0.f};
    int i = beg;
    for (; i + 3 < end; i += 4) {
        int2 e0 = __ldg(&g_edge[i]),     e1 = __ldg(&g_edge[i + 1]);
        int2 e2 = __ldg(&g_edge[i + 2]), e3 = __ldg(&g_edge[i + 3]);
        if (act) {
            uint2 u0 = __ldg(&h[(long long)e0.x * 25 + lane]);
            uint2 u1 = __ldg(&h[(long long)e1.x * 25 + lane]);
            uint2 u2 = __ldg(&h[(long long)e2.x * 25 + lane]);
            uint2 u3 = __ldg(&h[(long long)e3.x * 25 + lane]);
            float v0 = __int_as_float(e0.y), v1 = __int_as_float(e1.y);
            float v2 = __int_as_float(e2.y), v3 = __int_as_float(e3.y);
            float2 a0 = __half22float2(*(const __half2*)&u0.x);
            float2 b0 = __half22float2(*(const __half2*)&u0.y);
            float2 a1 = __half22float2(*(const __half2*)&u1.x);
            float2 b1 = __half22float2(*(const __half2*)&u1.y);
            float2 a2 = __half22float2(*(const __half2*)&u2.x);
            float2 b2 = __half22float2(*(const __half2*)&u2.y);
            float2 a3 = __half22float2(*(const __half2*)&u3.x);
            float2 b3 = __half22float2(*(const __half2*)&u3.y);
            acc[0] = fmaf(a0.x, v0, acc[0]); acc[1] = fmaf(a0.y, v0, acc[1]);
            acc[2] = fmaf(b0.x, v0, acc[2]); acc[3] = fmaf(b0.y, v0, acc[3]);
            acc[0] = fmaf(a1.x, v1, acc[0]); acc[1] = fmaf(a1.y, v1, acc[1]);
            acc[2] = fmaf(b1.x, v1, acc[2]); acc[3] = fmaf(b1.y, v1, acc[3]);
            acc[0] = fmaf(a2.x, v2, acc[0]); acc[1] = fmaf(a2.y, v2, acc[1]);
            acc[2] = fmaf(b2.x, v2, acc[2]); acc[3] = fmaf(b2.y, v2, acc[3]);
            acc[0] = fmaf(a3.x, v3, acc[0]); acc[1] = fmaf(a3.y, v3, acc[1]);
            acc[2] = fmaf(b3.x, v3, acc[2]); acc[3] = fmaf(b3.y, v3, acc[3]);
        }
    }
    for (; i < end; i++) {
        int2 e0 = __ldg(&g_edge[i]);
        if (act) {
            float v0 = __int_as_float(e0.y);
            uint2 u0 = __ldg(&h[(long long)e0.x * 25 + lane]);
            float2 a0 = __half22float2(*(const __half2*)&u0.x);
            float2 b0 = __half22float2(*(const __half2*)&u0.y);
            acc[0] = fmaf(a0.x, v0, acc[0]); acc[1] = fmaf(a0.y, v0, acc[1]);
            acc[2] = fmaf(b0.x, v0, acc[2]); acc[3] = fmaf(b0.y, v0, acc[3]);
        }
    }
    if (act) {
        __half2 h0 = __float22half2_rn(make_float2(acc[0], acc[1]));
        __half2 h1 = __float22half2_rn(make_float2(acc[2], acc[3]));
        uint2 u = make_uint2(*(unsigned*)&h0, *(unsigned*)&h1);
        *(uint2*)&out[(long long)r * 100 + lane * 4] = u;
    }
}

// ---------------- aggH: bufh[r,0:200] = fp16( sum h1h[src]*val ) -----------
__global__ void __launch_bounds__(256)
aggH_kernel(const uint4* __restrict__ h, uint4* __restrict__ out, int nRows) {
    const int g = threadIdx.x >> 5;
    const int lane = threadIdx.x & 31;
    const int r = blockIdx.x * 8 + g;
    if (r >= nRows) return;
    const bool act = lane < 25;
    const int beg = g_starts[r];
    const int end = g_starts[r + 1];

    float acc[8];
    #pragma unroll
    for (int c = 0; c < 8; c++) acc[c] = 0.f;

    int i = beg;
    for (; i + 3 < end; i += 4) {
        int2 e0 = __ldg(&g_edge[i]),     e1 = __ldg(&g_edge[i + 1]);
        int2 e2 = __ldg(&g_edge[i + 2]), e3 = __ldg(&g_edge[i + 3]);
        if (act) {
            uint4 u0 = __ldg(&h[(long long)e0.x * 25 + lane]);
            uint4 u1 = __ldg(&h[(long long)e1.x * 25 + lane]);
            uint4 u2 = __ldg(&h[(long long)e2.x * 25 + lane]);
            uint4 u3 = __ldg(&h[(long long)e3.x * 25 + lane]);
            float v0 = __int_as_float(e0.y), v1 = __int_as_float(e1.y);
            float v2 = __int_as_float(e2.y), v3 = __int_as_float(e3.y);
            const unsigned* w0 = &u0.x;
            const unsigned* w1 = &u1.x;
            const unsigned* w2 = &u2.x;
            const unsigned* w3 = &u3.x;
            #pragma unroll
            for (int q = 0; q < 4; q++) {
                float2 f0 = __half22float2(*(const __half2*)&w0[q]);
                float2 f1 = __half22float2(*(const __half2*)&w1[q]);
                float2 f2 = __half22float2(*(const __half2*)&w2[q]);
                float2 f3 = __half22float2(*(const __half2*)&w3[q]);
                acc[q * 2]     = fmaf(f0.x, v0, acc[q * 2]);
                acc[q * 2 + 1] = fmaf(f0.y, v0, acc[q * 2 + 1]);
                acc[q * 2]     = fmaf(f1.x, v1, acc[q * 2]);
                acc[q * 2 + 1] = fmaf(f1.y, v1, acc[q * 2 + 1]);
                acc[q * 2]     = fmaf(f2.x, v2, acc[q * 2]);
                acc[q * 2 + 1] = fmaf(f2.y, v2, acc[q * 2 + 1]);
                acc[q * 2]     = fmaf(f3.x, v3, acc[q * 2]);
                acc[q * 2 + 1] = fmaf(f3.y, v3, acc[q * 2 + 1]);
            }
        }
    }
    for (; i < end; i++) {
        int2 e0 = __ldg(&g_edge[i]);
        if (act) {
            float v0 = __int_as_float(e0.y);
            uint4 u0 = __ldg(&h[(long long)e0.x * 25 + lane]);
            const unsigned* w0 = &u0.x;
            #pragma unroll
            for (int q = 0; q < 4; q++) {
                float2 f0 = __half22float2(*(const __half2*)&w0[q]);
                acc[q * 2]     = fmaf(f0.x, v0, acc[q * 2]);
                acc[q * 2 + 1] = fmaf(f0.y, v0, acc[q * 2 + 1]);
            }
        }
    }
    if (act) {
        uint4 u;
        __half2 p0 = __float22half2_rn(make_float2(acc[0], acc[1]));
        __half2 p1 = __float22half2_rn(make_float2(acc[2], acc[3]));
        __half2 p2 = __float22half2_rn(make_float2(acc[4], acc[5]));
        __half2 p3 = __float22half2_rn(make_float2(acc[6], acc[7]));
        u.x = *(unsigned*)&p0; u.y = *(unsigned*)&p1;
        u.z = *(unsigned*)&p2; u.w = *(unsigned*)&p3;
        out[(long long)r * 25 + lane] = u;
    }
}

// ---------------- tf32 HMMA GEMM: C = postproc(A_half @ W_f32) -------------
#define CK 40
template <int K, int KP, bool LEAKY, bool NORM, bool HALF_OUT>
__global__ void __launch_bounds__(256)
gemm_tf32_kernel(const __half* __restrict__ A, const float* __restrict__ W,
                 void* __restrict__ Cv, int nRows) {
    __shared__ unsigned a_s[64][44];
    __shared__ unsigned w_s[CK][200];
    __shared__ float ssum[64][2];
    const int tid = threadIdx.x;
    const int wid = tid >> 5;
    const int lane = tid & 31;
    const int grp = lane >> 2;
    const int tig = lane & 3;
    const int wm = wid & 3;
    const int wn = wid >> 2;
    const int jbase = wn ? 13 : 0;
    const int jcount = wn ? 12 : 13;
    const int r0 = blockIdx.x * 64;

    float acc[13][4];
    #pragma unroll
    for (int j = 0; j < 13; j++)
        #pragma unroll
        for (int c = 0; c < 4; c++) acc[j][c] = 0.f;

    #pragma unroll
    for (int ch = 0; ch < KP / CK; ch++) {
        const int k0 = ch * CK;
        #pragma unroll
        for (int i = 0; i < 3; i++) {
            int idx4 = tid + i * 256;
            if (idx4 < 640) {
                int row = idx4 / 10;
                int q = idx4 % 10;
                int gr = r0 + row;
                float f[4] = {0.f, 0.f, 0.f, 0.f};
                if (gr < nRows && k0 + q * 4 < K) {
                    uint2 u = *(const uint2*)&A[(long long)gr * K + k0 + q * 4];
                    float2 a = __half22float2(*(const __half2*)&u.x);
                    float2 b = __half22float2(*(const __half2*)&u.y);
                    f[0] = a.x; f[1] = a.y; f[2] = b.x; f[3] = b.y;
                }
                a_s[row][q * 4 + 0] = tf32_of(f[0]);
                a_s[row][q * 4 + 1] = tf32_of(f[1]);
                a_s[row][q * 4 + 2] = tf32_of(f[2]);
                a_s[row][q * 4 + 3] = tf32_of(f[3]);
            }
        }
        #pragma unroll
        for (int i = 0; i < 8; i++) {
            int idx4 = tid + i * 256;
            if (idx4 < 2000) {
                int kk = idx4 / 50;
                int c4 = idx4 % 50;
                float4 v = make_float4(0.f, 0.f, 0.f, 0.f);
                if (k0 + kk < K)
                    v = *(const float4*)&W[(k0 + kk) * 200 + c4 * 4];
                w_s[kk][c4 * 4 + 0] = tf32_of(v.x);
                w_s[kk][c4 * 4 + 1] = tf32_of(v.y);
                w_s[kk][c4 * 4 + 2] = tf32_of(v.z);
                w_s[kk][c4 * 4 + 3] = tf32_of(v.w);
            }
        }
        __syncthreads();

        #pragma unroll
        for (int ks = 0; ks < CK / 8; ks++) {
            const int kk = ks * 8;
            unsigned a0 = a_s[wm * 16 + grp][kk + tig];
            unsigned a1 = a_s[wm * 16 + grp + 8][kk + tig];
            unsigned a2 = a_s[wm * 16 + grp][kk + tig + 4];
            unsigned a3 = a_s[wm * 16 + grp + 8][kk + tig + 4];
            #pragma unroll
            for (int j = 0; j < 13; j++) {
                if (j < jcount) {
                    int n0 = (jbase + j) * 8;
                    unsigned b0 = w_s[kk + tig][n0 + grp];
                    unsigned b1 = w_s[kk + tig + 4][n0 + grp];
                    mma_tf32(acc[j][0], acc[j][1], acc[j][2], acc[j][3],
                             a0, a1, a2, a3, b0, b1,
                             acc[j][0], acc[j][1], acc[j][2], acc[j][3]);
                }
            }
        }
        __syncthreads();
    }

    if (LEAKY || NORM) {
        #pragma unroll
        for (int j = 0; j < 13; j++) {
            if (j < jcount) {
                #pragma unroll
                for (int c = 0; c < 4; c++)
                    acc[j][c] = acc[j][c] > 0.f ? acc[j][c] : ALPHA * acc[j][c];
            }
        }
    }
    float inv_lo = 1.f, inv_hi = 1.f;
    if (NORM) {
        float slo = 0.f, shi = 0.f;
        #pragma unroll
        for (int j = 0; j < 13; j++) {
            if (j < jcount) {
                slo = fmaf(acc[j][0], acc[j][0], slo);
                slo = fmaf(acc[j][1], acc[j][1], slo);
                shi = fmaf(acc[j][2], acc[j][2], shi);
                shi = fmaf(acc[j][3], acc[j][3], shi);
            }
        }
        #pragma unroll
        for (int o = 1; o <= 2; o <<= 1) {
            slo += __shfl_xor_sync(0xffffffffu, slo, o);
            shi += __shfl_xor_sync(0xffffffffu, shi, o);
        }
        if (tig == 0) {
            ssum[wm * 16 + grp][wn] = slo;
            ssum[wm * 16 + grp + 8][wn] = shi;
        }
        __syncthreads();
        float tlo = ssum[wm * 16 + grp][0] + ssum[wm * 16 + grp][1];
        float thi = ssum[wm * 16 + grp + 8][0] + ssum[wm * 16 + grp + 8][1];
        inv_lo = 1.0f / fmaxf(sqrtf(tlo), EPSN);
        inv_hi = 1.0f / fmaxf(sqrtf(thi), EPSN);
    }

    const int row_lo = r0 + wm * 16 + grp;
    const int row_hi = row_lo + 8;
    #pragma unroll
    for (int j = 0; j < 13; j++) {
        if (j < jcount) {
            int col = (jbase + j) * 8 + tig * 2;
            float o0 = acc[j][0] * inv_lo, o1 = acc[j][1] * inv_lo;
            float o2 = acc[j][2] * inv_hi, o3 = acc[j][3] * inv_hi;
            if (HALF_OUT) {
                __half* C = (__half*)Cv;
                __half2 plo = __float22half2_rn(make_float2(o0, o1));
                __half2 phi = __float22half2_rn(make_float2(o2, o3));
                if (row_lo < nRows) *(__half2*)&C[(long long)row_lo * 200 + col] = plo;
                if (row_hi < nRows) *(__half2*)&C[(long long)row_hi * 200 + col] = phi;
            } else {
                float* C = (float*)Cv;
                if (row_lo < nRows) *(float2*)&C[(long long)row_lo * 200 + col] = make_float2(o0, o1);
                if (row_hi < nRows) *(float2*)&C[(long long)row_hi * 200 + col] = make_float2(o2, o3);
            }
        }
    }
}

// ---------------- launch ----------------
extern "C" void kernel_launch(void* const* d_in, const int* in_sizes, int n_in,
                              void* d_out, int out_size) {
    const float* emb = (const float*)d_in[0];        // [N_TOT, 100]
    const float* W1  = (const float*)d_in[1];        // [100, 200]
    const float* W2  = (const float*)d_in[2];        // [200, 200]
    const void*  ei  = d_in[3];                      // [2, E]
    const float* ev  = (const float*)d_in[4];        // [E]
    float* out = (float*)d_out;                      // [N_TOT, 200]

    __half* embh; cudaGetSymbolAddress((void**)&embh, g_embh);
    __half* bufh; cudaGetSymbolAddress((void**)&bufh, g_bufh);
    __half* h1h;  cudaGetSymbolAddress((void**)&h1h, g_h1h);

    // CSR build (+ fused emb->fp16 conversion in hist)
    hist_kernel<<<(E_NUM / 4 + 255) / 256, 256>>>(ei, (const float2*)emb);
    scan_kernel<<<SCAN_NB, SCAN_BLK>>>();
    scatter_kernel<<<(E_NUM / 4 + 255) / 256, 256>>>(ei, ev);

    int ggrid = (N_TOT + 63) / 64;

    // Layer 1: agg(emb fp16) -> fp16; gemm1(+leaky) -> h1 fp16
    agg1_kernel<<<(N_TOT + 7) / 8, 256>>>((const uint2*)embh, bufh, N_TOT);
    gemm_tf32_kernel<D_IN, 120, true, false, true><<<ggrid, 256>>>(bufh, W1, h1h, N_TOT);

    // Layer 2: agg(h1 fp16) -> fp16; gemm2(+leaky+norm) -> d_out fp32
    aggH_kernel<<<(N_TOT + 7) / 8, 256>>>((const uint4*)h1h, (uint4*)bufh, N_TOT);
    gemm_tf32_kernel<D_OUT, 200, true, true, false><<<ggrid, 256>>>(bufh, W2, out, N_TOT);
}

// round 8
// speedup vs baseline: 2.4429x; 1.0271x over previous
#include <cuda_runtime.h>
#include <cuda_fp16.h>
#include <cstdint>

#define N_ENT 50000
#define N_REL 500
#define N_TOT (N_ENT + N_REL)   // 50500
#define E_NUM 800000
#define D_IN  100
#define D_OUT 200
#define ALPHA 0.2f
#define EPSN  1e-12f

#define SCAN_BLK 1024
#define SCAN_NB  ((N_TOT + SCAN_BLK - 1) / SCAN_BLK)   // 50

// ---------------- scratch (device globals; zero-initialized at load) -------
__device__ __half g_embh[N_TOT * D_IN];   // fp16 embeddings
__device__ __half g_w1t[D_OUT * D_IN];    // W1^T fp16: [200][100]
__device__ __half g_w2t[D_OUT * D_OUT];   // W2^T fp16: [200][200]
__device__ __half g_bufh[N_TOT * D_OUT];  // agg1 out [N,100] / aggH out [N,200]
__device__ __half g_h1h[N_TOT * D_OUT];   // layer-1 output [N,200]
__device__ int    g_counts[N_TOT];
__device__ int    g_starts[N_TOT + 1];
__device__ int    g_cursor[N_TOT];
__device__ int    g_bsum[SCAN_NB];
__device__ int    g_flag[SCAN_NB];
__device__ int2   g_edge[E_NUM];          // dst-sorted (src, val_bits)

// ---------------- helpers ----------------
__device__ __forceinline__ int detect_is64_block(const int* ei_words) {
    __shared__ int s_is64;
    if (threadIdx.x == 0) {
        int f = 1;
        #pragma unroll 8
        for (int j = 1; j < 256; j += 2)
            if (ei_words[j] != 0) f = 0;
        s_is64 = f;
    }
    __syncthreads();
    return s_is64;
}
__device__ __forceinline__ void mma_f16_k16(
    float& d0, float& d1, float& d2, float& d3,
    unsigned a0, unsigned a1, unsigned a2, unsigned a3,
    unsigned b0, unsigned b1,
    float c0, float c1, float c2, float c3) {
    asm("mma.sync.aligned.m16n8k16.row.col.f32.f16.f16.f32 "
        "{%0,%1,%2,%3},{%4,%5,%6,%7},{%8,%9},{%10,%11,%12,%13};"
        : "=f"(d0), "=f"(d1), "=f"(d2), "=f"(d3)
        : "r"(a0), "r"(a1), "r"(a2), "r"(a3), "r"(b0), "r"(b1),
          "f"(c0), "f"(c1), "f"(c2), "f"(c3));
}
__device__ __forceinline__ void mma_f16_k8(
    float& d0, float& d1, float& d2, float& d3,
    unsigned a0, unsigned a1, unsigned b0,
    float c0, float c1, float c2, float c3) {
    asm("mma.sync.aligned.m16n8k8.row.col.f32.f16.f16.f32 "
        "{%0,%1,%2,%3},{%4,%5},{%6},{%7,%8,%9,%10};"
        : "=f"(d0), "=f"(d1), "=f"(d2), "=f"(d3)
        : "r"(a0), "r"(a1), "r"(b0),
          "f"(c0), "f"(c1), "f"(c2), "f"(c3));
}
__device__ __forceinline__ void load_idx4(const void* ei, long long base, int e4,
                                          int is64, int d[4]) {
    if (is64) {
        const longlong2* p = (const longlong2*)ei;
        long long off = (base + 4LL * e4) >> 1;
        longlong2 a = __ldg(&p[off]);
        longlong2 b = __ldg(&p[off + 1]);
        d[0] = (int)a.x; d[1] = (int)a.y; d[2] = (int)b.x; d[3] = (int)b.y;
    } else {
        const int4* p = (const int4*)ei;
        int4 a = __ldg(&p[(base + 4LL * e4) >> 2]);
        d[0] = a.x; d[1] = a.y; d[2] = a.z; d[3] = a.w;
    }
}

// -------- hist + fp16 conversions (emb, W1^T, W2^T) fused ------------------
__global__ void __launch_bounds__(256)
hist_kernel(const void* __restrict__ ei, const float2* __restrict__ emb,
            const float* __restrict__ W1, const float* __restrict__ W2) {
    int is64 = detect_is64_block((const int*)ei);
    if (blockIdx.x == 0 && threadIdx.x < SCAN_NB) g_flag[threadIdx.x] = 0;
    int gtid = blockIdx.x * blockDim.x + threadIdx.x;
    if (gtid < E_NUM / 4) {
        int d[4];
        load_idx4(ei, E_NUM, gtid, is64, d);
        atomicAdd(&g_counts[d[0]], 1);
        atomicAdd(&g_counts[d[1]], 1);
        atomicAdd(&g_counts[d[2]], 1);
        atomicAdd(&g_counts[d[3]], 1);
    }
    const int stride = gridDim.x * blockDim.x;
    // emb fp32 -> fp16
    __half2* dst = (__half2*)g_embh;
    const int total2 = N_TOT * D_IN / 2;
    for (int i = gtid; i < total2; i += stride)
        dst[i] = __float22half2_rn(__ldg(&emb[i]));
    // W1 -> W1^T fp16
    for (int i = gtid; i < D_IN * D_OUT; i += stride) {
        int k = i / D_OUT, n = i % D_OUT;
        g_w1t[n * D_IN + k] = __float2half_rn(__ldg(&W1[i]));
    }
    // W2 -> W2^T fp16
    for (int i = gtid; i < D_OUT * D_OUT; i += stride) {
        int k = i / D_OUT, n = i % D_OUT;
        g_w2t[n * D_OUT + k] = __float2half_rn(__ldg(&W2[i]));
    }
}

// ---------------- single-pass scan with decoupled lookback -----------------
__global__ void __launch_bounds__(SCAN_BLK)
scan_kernel() {
    __shared__ int woff[32];
    __shared__ int s_off[2];
    const int tid = threadIdx.x;
    const int lane = tid & 31;
    const int wid = tid >> 5;
    const int b = blockIdx.x;
    const int i = b * SCAN_BLK + tid;

    int v = (i < N_TOT) ? g_counts[i] : 0;
    if (i < N_TOT) g_counts[i] = 0;

    int incl = v;
    #pragma unroll
    for (int o = 1; o < 32; o <<= 1) {
        int t = __shfl_up_sync(0xffffffffu, incl, o);
        if (lane >= o) incl += t;
    }
    if (lane == 31) woff[wid] = incl;
    __syncthreads();
    if (wid == 0) {
        int w = woff[lane];
        int wincl = w;
        #pragma unroll
        for (int o = 1; o < 32; o <<= 1) {
            int t = __shfl_up_sync(0xffffffffu, wincl, o);
            if (lane >= o) wincl += t;
        }
        woff[lane] = wincl - w;
        if (lane == 31) {
            g_bsum[b] = wincl;
            __threadfence();
            atomicExch(&g_flag[b], 1);
        }
    }
    __syncthreads();

    if (tid < 64) {
        int offv = 0;
        if (tid < b) {
            while (atomicAdd(&g_flag[tid], 0) == 0) { }
            __threadfence();
            offv = g_bsum[tid];
        }
        #pragma unroll
        for (int o = 16; o; o >>= 1) offv += __shfl_down_sync(0xffffffffu, offv, o);
        if ((tid & 31) == 0) s_off[tid >> 5] = offv;
    }
    __syncthreads();
    int off = s_off[0] + s_off[1];

    if (i < N_TOT) {
        int s = off + woff[wid] + (incl - v);
        g_starts[i] = s;
        g_cursor[i] = s;
    }
    if (b == SCAN_NB - 1 && tid == 0)
        g_starts[N_TOT] = off + g_bsum[b];
}

// ---------------- scatter ---------------------------------------------------
__global__ void __launch_bounds__(256)
scatter_kernel(const void* __restrict__ ei, const float* __restrict__ ev) {
    int is64 = detect_is64_block((const int*)ei);
    int e4 = blockIdx.x * blockDim.x + threadIdx.x;
    if (e4 < E_NUM / 4) {
        int s[4], d[4];
        load_idx4(ei, 0, e4, is64, s);
        load_idx4(ei, E_NUM, e4, is64, d);
        float4 v = __ldg(&((const float4*)ev)[e4]);
        int p0 = atomicAdd(&g_cursor[d[0]], 1);
        int p1 = atomicAdd(&g_cursor[d[1]], 1);
        int p2 = atomicAdd(&g_cursor[d[2]], 1);
        int p3 = atomicAdd(&g_cursor[d[3]], 1);
        g_edge[p0] = make_int2(s[0], __float_as_int(v.x));
        g_edge[p1] = make_int2(s[1], __float_as_int(v.y));
        g_edge[p2] = make_int2(s[2], __float_as_int(v.z));
        g_edge[p3] = make_int2(s[3], __float_as_int(v.w));
    }
}

// ---------------- agg1: bufh[r,0:100] = fp16( sum embh[src]*val ) ----------
__global__ void __launch_bounds__(256)
agg1_kernel(const uint2* __restrict__ h, __half* __restrict__ out, int nRows) {
    const int g = threadIdx.x >> 5;
    const int lane = threadIdx.x & 31;
    const int r = blockIdx.x * 8 + g;
    if (r >= nRows) return;
    const bool act = lane < 25;
    const int beg = g_starts[r];
    const int end = g_starts[r + 1];

    float acc[4] = {0.f, 0.f, 0.f, 0.f};
    int i = beg;
    for (; i + 3 < end; i += 4) {
        int2 e0 = __ldg(&g_edge[i]),     e1 = __ldg(&g_edge[i + 1]);
        int2 e2 = __ldg(&g_edge[i + 2]), e3 = __ldg(&g_edge[i + 3]);
        if (act) {
            uint2 u0 = __ldg(&h[(long long)e0.x * 25 + lane]);
            uint2 u1 = __ldg(&h[(long long)e1.x * 25 + lane]);
            uint2 u2 = __ldg(&h[(long long)e2.x * 25 + lane]);
            uint2 u3 = __ldg(&h[(long long)e3.x * 25 + lane]);
            float v0 = __int_as_float(e0.y), v1 = __int_as_float(e1.y);
            float v2 = __int_as_float(e2.y), v3 = __int_as_float(e3.y);
            float2 a0 = __half22float2(*(const __half2*)&u0.x);
            float2 b0 = __half22float2(*(const __half2*)&u0.y);
            float2 a1 = __half22float2(*(const __half2*)&u1.x);
            float2 b1 = __half22float2(*(const __half2*)&u1.y);
            float2 a2 = __half22float2(*(const __half2*)&u2.x);
            float2 b2 = __half22float2(*(const __half2*)&u2.y);
            float2 a3 = __half22float2(*(const __half2*)&u3.x);
            float2 b3 = __half22float2(*(const __half2*)&u3.y);
            acc[0] = fmaf(a0.x, v0, acc[0]); acc[1] = fmaf(a0.y, v0, acc[1]);
            acc[2] = fmaf(b0.x, v0, acc[2]); acc[3] = fmaf(b0.y, v0, acc[3]);
            acc[0] = fmaf(a1.x, v1, acc[0]); acc[1] = fmaf(a1.y, v1, acc[1]);
            acc[2] = fmaf(b1.x, v1, acc[2]); acc[3] = fmaf(b1.y, v1, acc[3]);
            acc[0] = fmaf(a2.x, v2, acc[0]); acc[1] = fmaf(a2.y, v2, acc[1]);
            acc[2] = fmaf(b2.x, v2, acc[2]); acc[3] = fmaf(b2.y, v2, acc[3]);
            acc[0] = fmaf(a3.x, v3, acc[0]); acc[1] = fmaf(a3.y, v3, acc[1]);
            acc[2] = fmaf(b3.x, v3, acc[2]); acc[3] = fmaf(b3.y, v3, acc[3]);
        }
    }
    for (; i < end; i++) {
        int2 e0 = __ldg(&g_edge[i]);
        if (act) {
            float v0 = __int_as_float(e0.y);
            uint2 u0 = __ldg(&h[(long long)e0.x * 25 + lane]);
            float2 a0 = __half22float2(*(const __half2*)&u0.x);
            float2 b0 = __half22float2(*(const __half2*)&u0.y);
            acc[0] = fmaf(a0.x, v0, acc[0]); acc[1] = fmaf(a0.y, v0, acc[1]);
            acc[2] = fmaf(b0.x, v0, acc[2]); acc[3] = fmaf(b0.y, v0, acc[3]);
        }
    }
    if (act) {
        __half2 h0 = __float22half2_rn(make_float2(acc[0], acc[1]));
        __half2 h1 = __float22half2_rn(make_float2(acc[2], acc[3]));
        uint2 u = make_uint2(*(unsigned*)&h0, *(unsigned*)&h1);
        *(uint2*)&out[(long long)r * 100 + lane * 4] = u;
    }
}

// ---------------- aggH: bufh[r,0:200] = fp16( sum h1h[src]*val ) -----------
__global__ void __launch_bounds__(256)
aggH_kernel(const uint4* __restrict__ h, uint4* __restrict__ out, int nRows) {
    const int g = threadIdx.x >> 5;
    const int lane = threadIdx.x & 31;
    const int r = blockIdx.x * 8 + g;
    if (r >= nRows) return;
    const bool act = lane < 25;
    const int beg = g_starts[r];
    const int end = g_starts[r + 1];

    float acc[8];
    #pragma unroll
    for (int c = 0; c < 8; c++) acc[c] = 0.f;

    int i = beg;
    for (; i + 3 < end; i += 4) {
        int2 e0 = __ldg(&g_edge[i]),     e1 = __ldg(&g_edge[i + 1]);
        int2 e2 = __ldg(&g_edge[i + 2]), e3 = __ldg(&g_edge[i + 3]);
        if (act) {
            uint4 u0 = __ldg(&h[(long long)e0.x * 25 + lane]);
            uint4 u1 = __ldg(&h[(long long)e1.x * 25 + lane]);
            uint4 u2 = __ldg(&h[(long long)e2.x * 25 + lane]);
            uint4 u3 = __ldg(&h[(long long)e3.x * 25 + lane]);
            float v0 = __int_as_float(e0.y), v1 = __int_as_float(e1.y);
            float v2 = __int_as_float(e2.y), v3 = __int_as_float(e3.y);
            const unsigned* w0 = &u0.x;
            const unsigned* w1 = &u1.x;
            const unsigned* w2 = &u2.x;
            const unsigned* w3 = &u3.x;
            #pragma unroll
            for (int q = 0; q < 4; q++) {
                float2 f0 = __half22float2(*(const __half2*)&w0[q]);
                float2 f1 = __half22float2(*(const __half2*)&w1[q]);
                float2 f2 = __half22float2(*(const __half2*)&w2[q]);
                float2 f3 = __half22float2(*(const __half2*)&w3[q]);
                acc[q * 2]     = fmaf(f0.x, v0, acc[q * 2]);
                acc[q * 2 + 1] = fmaf(f0.y, v0, acc[q * 2 + 1]);
                acc[q * 2]     = fmaf(f1.x, v1, acc[q * 2]);
                acc[q * 2 + 1] = fmaf(f1.y, v1, acc[q * 2 + 1]);
                acc[q * 2]     = fmaf(f2.x, v2, acc[q * 2]);
                acc[q * 2 + 1] = fmaf(f2.y, v2, acc[q * 2 + 1]);
                acc[q * 2]     = fmaf(f3.x, v3, acc[q * 2]);
                acc[q * 2 + 1] = fmaf(f3.y, v3, acc[q * 2 + 1]);
            }
        }
    }
    for (; i < end; i++) {
        int2 e0 = __ldg(&g_edge[i]);
        if (act) {
            float v0 = __int_as_float(e0.y);
            uint4 u0 = __ldg(&h[(long long)e0.x * 25 + lane]);
            const unsigned* w0 = &u0.x;
            #pragma unroll
            for (int q = 0; q < 4; q++) {
                float2 f0 = __half22float2(*(const __half2*)&w0[q]);
                acc[q * 2]     = fmaf(f0.x, v0, acc[q * 2]);
                acc[q * 2 + 1] = fmaf(f0.y, v0, acc[q * 2 + 1]);
            }
        }
    }
    if (act) {
        uint4 u;
        __half2 p0 = __float22half2_rn(make_float2(acc[0], acc[1]));
        __half2 p1 = __float22half2_rn(make_float2(acc[2], acc[3]));
        __half2 p2 = __float22half2_rn(make_float2(acc[4], acc[5]));
        __half2 p3 = __float22half2_rn(make_float2(acc[6], acc[7]));
        u.x = *(unsigned*)&p0; u.y = *(unsigned*)&p1;
        u.z = *(unsigned*)&p2; u.w = *(unsigned*)&p3;
        out[(long long)r * 25 + lane] = u;
    }
}

// ---------------- fp16 HMMA GEMM: C = postproc(A_half @ Wt_half^T) ---------
// Block 256 thr = 8 warps (4 over M=64, 2 over N: 13+12 n8-tiles).
// K-chunks of 40: 2x m16n8k16 + 1x m16n8k8 per chunk.
#define CK 40
#define APAD 52   // a_s row stride in halves (104B -> conflict-spread)
template <int K, int KP, bool LEAKY, bool NORM, bool HALF_OUT>
__global__ void __launch_bounds__(256)
gemm_f16_kernel(const __half* __restrict__ A, const __half* __restrict__ Wt,
                void* __restrict__ Cv, int nRows) {
    __shared__ __half a_s[64][APAD];
    __shared__ __half w_s[200][APAD];
    __shared__ float ssum[64][2];
    const int tid = threadIdx.x;
    const int wid = tid >> 5;
    const int lane = tid & 31;
    const int grp = lane >> 2;
    const int tig = lane & 3;
    const int wm = wid & 3;
    const int wn = wid >> 2;
    const int jbase = wn ? 13 : 0;
    const int jcount = wn ? 12 : 13;
    const int r0 = blockIdx.x * 64;

    float acc[13][4];
    #pragma unroll
    for (int j = 0; j < 13; j++)
        #pragma unroll
        for (int c = 0; c < 4; c++) acc[j][c] = 0.f;

    #pragma unroll
    for (int ch = 0; ch < KP / CK; ch++) {
        const int k0 = ch * CK;
        // stage A chunk: 64 rows x 40 halves (uint2 = 4 halves), no cvt
        #pragma unroll
        for (int i = 0; i < 3; i++) {
            int idx4 = tid + i * 256;
            if (idx4 < 640) {
                int row = idx4 / 10;
                int q = idx4 % 10;
                int gr = r0 + row;
                uint2 u = make_uint2(0u, 0u);
                if (gr < nRows && k0 + q * 4 < K)
                    u = *(const uint2*)&A[(long long)gr * K + k0 + q * 4];
                *(uint2*)&a_s[row][q * 4] = u;
            }
        }
        // stage W chunk: 200 n-rows x 40 halves from transposed fp16 W
        #pragma unroll
        for (int i = 0; i < 8; i++) {
            int idx4 = tid + i * 256;
            if (idx4 < 2000) {
                int n = idx4 / 10;
                int q = idx4 % 10;
                uint2 u = make_uint2(0u, 0u);
                if (k0 + q * 4 < K)
                    u = *(const uint2*)&Wt[(long long)n * K + k0 + q * 4];
                *(uint2*)&w_s[n][q * 4] = u;
            }
        }
        __syncthreads();

        const int arow = wm * 16 + grp;
        // 2x k16 steps
        #pragma unroll
        for (int ks = 0; ks < 2; ks++) {
            const int kk = ks * 16;
            unsigned a0 = *(const unsigned*)&a_s[arow][kk + 2 * tig];
            unsigned a1 = *(const unsigned*)&a_s[arow + 8][kk + 2 * tig];
            unsigned a2 = *(const unsigned*)&a_s[arow][kk + 2 * tig + 8];
            unsigned a3 = *(const unsigned*)&a_s[arow + 8][kk + 2 * tig + 8];
            #pragma unroll
            for (int j = 0; j < 13; j++) {
                if (j < jcount) {
                    int n = (jbase + j) * 8 + grp;
                    unsigned b0 = *(const unsigned*)&w_s[n][kk + 2 * tig];
                    unsigned b1 = *(const unsigned*)&w_s[n][kk + 2 * tig + 8];
                    mma_f16_k16(acc[j][0], acc[j][1], acc[j][2], acc[j][3],
                                a0, a1, a2, a3, b0, b1,
                                acc[j][0], acc[j][1], acc[j][2], acc[j][3]);
                }
            }
        }
        // k8 tail (k 32..39)
        {
            unsigned a0 = *(const unsigned*)&a_s[arow][32 + 2 * tig];
            unsigned a1 = *(const unsigned*)&a_s[arow + 8][32 + 2 * tig];
            #pragma unroll
            for (int j = 0; j < 13; j++) {
                if (j < jcount) {
                    int n = (jbase + j) * 8 + grp;
                    unsigned b0 = *(const unsigned*)&w_s[n][32 + 2 * tig];
                    mma_f16_k8(acc[j][0], acc[j][1], acc[j][2], acc[j][3],
                               a0, a1, b0,
                               acc[j][0], acc[j][1], acc[j][2], acc[j][3]);
                }
            }
        }
        __syncthreads();
    }

    if (LEAKY || NORM) {
        #pragma unroll
        for (int j = 0; j < 13; j++) {
            if (j < jcount) {
                #pragma unroll
                for (int c = 0; c < 4; c++)
                    acc[j][c] = acc[j][c] > 0.f ? acc[j][c] : ALPHA * acc[j][c];
            }
        }
    }
    float inv_lo = 1.f, inv_hi = 1.f;
    if (NORM) {
        float slo = 0.f, shi = 0.f;
        #pragma unroll
        for (int j = 0; j < 13; j++) {
            if (j < jcount) {
                slo = fmaf(acc[j][0], acc[j][0], slo);
                slo = fmaf(acc[j][1], acc[j][1], slo);
                shi = fmaf(acc[j][2], acc[j][2], shi);
                shi = fmaf(acc[j][3], acc[j][3], shi);
            }
        }
        #pragma unroll
        for (int o = 1; o <= 2; o <<= 1) {
            slo += __shfl_xor_sync(0xffffffffu, slo, o);
            shi += __shfl_xor_sync(0xffffffffu, shi, o);
        }
        if (tig == 0) {
            ssum[wm * 16 + grp][wn] = slo;
            ssum[wm * 16 + grp + 8][wn] = shi;
        }
        __syncthreads();
        float tlo = ssum[wm * 16 + grp][0] + ssum[wm * 16 + grp][1];
        float thi = ssum[wm * 16 + grp + 8][0] + ssum[wm * 16 + grp + 8][1];
        inv_lo = 1.0f / fmaxf(sqrtf(tlo), EPSN);
        inv_hi = 1.0f / fmaxf(sqrtf(thi), EPSN);
    }

    const int row_lo = r0 + wm * 16 + grp;
    const int row_hi = row_lo + 8;
    #pragma unroll
    for (int j = 0; j < 13; j++) {
        if (j < jcount) {
            int col = (jbase + j) * 8 + tig * 2;
            float o0 = acc[j][0] * inv_lo, o1 = acc[j][1] * inv_lo;
            float o2 = acc[j][2] * inv_hi, o3 = acc[j][3] * inv_hi;
            if (HALF_OUT) {
                __half* C = (__half*)Cv;
                __half2 plo = __float22half2_rn(make_float2(o0, o1));
                __half2 phi = __float22half2_rn(make_float2(o2, o3));
                if (row_lo < nRows) *(__half2*)&C[(long long)row_lo * 200 + col] = plo;
                if (row_hi < nRows) *(__half2*)&C[(long long)row_hi * 200 + col] = phi;
            } else {
                float* C = (float*)Cv;
                if (row_lo < nRows) *(float2*)&C[(long long)row_lo * 200 + col] = make_float2(o0, o1);
                if (row_hi < nRows) *(float2*)&C[(long long)row_hi * 200 + col] = make_float2(o2, o3);
            }
        }
    }
}

// ---------------- launch ----------------
extern "C" void kernel_launch(void* const* d_in, const int* in_sizes, int n_in,
                              void* d_out, int out_size) {
    const float* emb = (const float*)d_in[0];        // [N_TOT, 100]
    const float* W1  = (const float*)d_in[1];        // [100, 200]
    const float* W2  = (const float*)d_in[2];        // [200, 200]
    const void*  ei  = d_in[3];                      // [2, E]
    const float* ev  = (const float*)d_in[4];        // [E]
    float* out = (float*)d_out;                      // [N_TOT, 200]

    __half* embh; cudaGetSymbolAddress((void**)&embh, g_embh);
    __half* w1t;  cudaGetSymbolAddress((void**)&w1t, g_w1t);
    __half* w2t;  cudaGetSymbolAddress((void**)&w2t, g_w2t);
    __half* bufh; cudaGetSymbolAddress((void**)&bufh, g_bufh);
    __half* h1h;  cudaGetSymbolAddress((void**)&h1h, g_h1h);

    // CSR build + all fp16 conversions
    hist_kernel<<<(E_NUM / 4 + 255) / 256, 256>>>(ei, (const float2*)emb, W1, W2);
    scan_kernel<<<SCAN_NB, SCAN_BLK>>>();
    scatter_kernel<<<(E_NUM / 4 + 255) / 256, 256>>>(ei, ev);

    int ggrid = (N_TOT + 63) / 64;

    // Layer 1: agg(emb fp16) -> fp16; gemm1(+leaky) -> h1 fp16
    agg1_kernel<<<(N_TOT + 7) / 8, 256>>>((const uint2*)embh, bufh, N_TOT);
    gemm_f16_kernel<D_IN, 120, true, false, true><<<ggrid, 256>>>(bufh, w1t, h1h, N_TOT);

    // Layer 2: agg(h1 fp16) -> fp16; gemm2(+leaky+norm) -> d_out fp32
    aggH_kernel<<<(N_TOT + 7) / 8, 256>>>((const uint4*)h1h, (uint4*)bufh, N_TOT);
    gemm_f16_kernel<D_OUT, 200, true, true, false><<<ggrid, 256>>>(bufh, w2t, out, N_TOT);
}